// round 14
// baseline (speedup 1.0000x reference)
#include <cuda_runtime.h>
#include <cuda_fp16.h>

#define NN 100000
#define EE 1600000
#define FIN 100
#define D 64
#define GG 500
#define SCAN_T 512
#define SCAN_NB ((NN + SCAN_T - 1) / SCAN_T)
#define APAD 132
#define AGB 12500                 // agg blocks per layer (8 nodes each)
#define GB2 1563                  // 64-row gemm tiles: (NN+63)/64
#define GPAD 72                   // smem pad for 64-row staging

// ---------------- scratch (device globals; no allocs allowed) ----------------
__device__ float g_deg[NN];
__device__ int   g_cntn[NN];
__device__ int   g_ptr[NN + 1];
__device__ int   g_partials[SCAN_NB];
__device__ int2  g_csr[EE];        // packed {row, norm_bits}
__device__ float g_out0[NN * D];
__device__ uint4 g_h1[NN * 8];     // per-stage fp16 h buffers (no reuse within a
__device__ uint4 g_h2[NN * 8];     //  launch -> no stale-L1 hazard)
__device__ uint4 g_h3[NN * 8];
__device__ uint4 g_h4[NN * 8];
__device__ float g_aggA[NN * D];
__device__ float g_aggB[NN * D];
__device__ float g_aggC[NN * D];
__device__ float g_sums[GG * D];
__device__ float g_cnt[GG];
__device__ int g_is64_edge;
__device__ int g_is64_batch;
__device__ int g_scan_ctr;
__device__ int g_scan_done;
__device__ int g_tileCnt[3][GB2];  // per-gemm-tile agg completion counters
__device__ int g_gemmDone[3];      // per-layer gemm completion counters

__device__ __forceinline__ int load_idx(const void* p, long long i, int is64) {
    return is64 ? (int)((const long long*)p)[i] : ((const int*)p)[i];
}

// ptr fixup inlined: final ptr(n) = g_ptr[n] + partials[n>>9]
__device__ __forceinline__ int ptr_of(int n) {
    return (n == NN) ? EE : g_ptr[n] + g_partials[n >> 9];
}

// ---------------- init: zero scratch + dtype detect (one kernel) -------------
__global__ void init_kernel(const int* ei, const int* bat) {
    int t = blockIdx.x * 256 + threadIdx.x;
    if (t < NN) { g_deg[t] = 0.f; g_cntn[t] = 0; }
    if (t < GG * D) g_sums[t] = 0.f;
    if (t < GG) g_cnt[t] = 0.f;
    if (t < 3 * GB2) ((int*)g_tileCnt)[t] = 0;
    if (t < 3) g_gemmDone[t] = 0;
    if (t == 0) { g_scan_ctr = 0; g_scan_done = 0; }
    if (blockIdx.x == 0 && threadIdx.x < 32) {
        int i = threadIdx.x;
        int nz_e = 0, nz_b = 0;
        for (int j = i; j < 128; j += 32) {
            int w = 1 + 700 * j;  // always odd, < NN words
            nz_e |= (ei[w] != 0);
            nz_b |= (bat[w] != 0);
        }
        unsigned be = __ballot_sync(0xffffffffu, nz_e);
        unsigned bb = __ballot_sync(0xffffffffu, nz_b);
        if (i == 0) {
            g_is64_edge = (be == 0);
            g_is64_batch = (bb == 0);
        }
    }
}

// ---------------- fused: lin0 GEMM (fp32, R7 schedule) + degree histogram ----
__global__ void fused_lin0_deg(const float* __restrict__ A, const float* __restrict__ W,
                               const float* __restrict__ biasC, float* __restrict__ C,
                               const void* ei, const float* __restrict__ ew,
                               int gemm_blocks) {
    __shared__ float Ws[FIN * D];
    __shared__ float As[20 * APAD];
    int tid = threadIdx.x;

    if (blockIdx.x >= gemm_blocks) {
        int base = (blockIdx.x - gemm_blocks) * 1024 + tid;
        int is64 = g_is64_edge;
        int c[4]; float w[4];
#pragma unroll
        for (int j = 0; j < 4; j++) {
            int e = base + j * 256;
            if (e < EE) {
                c[j] = load_idx(ei, (long long)EE + e, is64);
                w[j] = ew[e];
            } else c[j] = -1;
        }
#pragma unroll
        for (int j = 0; j < 4; j++) {
            if (c[j] >= 0) {
                atomicAdd(&g_deg[c[j]], w[j]);
                atomicAdd(&g_cntn[c[j]], 1);
            }
        }
        return;
    }

    int row0 = blockIdx.x * 128;
    for (int i = tid; i < FIN * D; i += 256) Ws[i] = W[i];
    int tx = tid & 15, ty = tid >> 4;
    float acc[8][4] = {};

    for (int kb = 0; kb < FIN; kb += 20) {
        __syncthreads();  // also guards Ws on first iteration
        for (int i = tid; i < 128 * 20; i += 256) {
            int rr = i / 20, kk = i - rr * 20;
            int r = row0 + rr;
            As[kk * APAD + rr] = (r < NN) ? A[(long long)r * FIN + kb + kk] : 0.f;
        }
        __syncthreads();
#pragma unroll
        for (int k = 0; k < 20; k++) {
            float4 a0 = *(const float4*)&As[k * APAD + ty * 8];
            float4 a1 = *(const float4*)&As[k * APAD + ty * 8 + 4];
            float4 wv = *(const float4*)&Ws[(kb + k) * D + tx * 4];
            float av[8] = {a0.x, a0.y, a0.z, a0.w, a1.x, a1.y, a1.z, a1.w};
#pragma unroll
            for (int i2 = 0; i2 < 8; i2++) {
                acc[i2][0] += av[i2] * wv.x;
                acc[i2][1] += av[i2] * wv.y;
                acc[i2][2] += av[i2] * wv.z;
                acc[i2][3] += av[i2] * wv.w;
            }
        }
    }
    int c0 = tx * 4;
    float4 bc = *(const float4*)&biasC[c0];
#pragma unroll
    for (int i2 = 0; i2 < 8; i2++) {
        int r = row0 + ty * 8 + i2;
        if (r >= NN) break;
        float4 v = make_float4(fmaxf(acc[i2][0] + bc.x, 0.f), fmaxf(acc[i2][1] + bc.y, 0.f),
                               fmaxf(acc[i2][2] + bc.z, 0.f), fmaxf(acc[i2][3] + bc.w, 0.f));
        *(float4*)&C[(long long)r * D + c0] = v;
    }
}

// ---------------- mega kernel: [scan | conv0 GEMM | scatter] (unchanged) -----
__global__ void mega_conv0(const float* __restrict__ A, const float* __restrict__ W,
                           unsigned* __restrict__ hout,
                           const void* ei, const float* __restrict__ ew,
                           int gemm_blocks) {
    __shared__ float Ws[D * D];
    __shared__ float As[32 * APAD];
    __shared__ int sh[256];
    __shared__ int is_last;
    int tid = threadIdx.x;
    int bid = blockIdx.x;

    if (bid < SCAN_NB) {
        int i0 = bid * SCAN_T + 2 * tid;
        int a = (i0 < NN) ? g_cntn[i0] : 0;
        int b = (i0 + 1 < NN) ? g_cntn[i0 + 1] : 0;
        sh[tid] = a + b;
        __syncthreads();
        for (int off = 1; off < 256; off <<= 1) {
            int t = (tid >= off) ? sh[tid - off] : 0;
            __syncthreads();
            sh[tid] += t;
            __syncthreads();
        }
        int excl = sh[tid] - (a + b);
        if (i0 < NN) g_ptr[i0] = excl;
        if (i0 + 1 < NN) g_ptr[i0 + 1] = excl + a;
        if (tid == 255) {
            g_partials[bid] = sh[255];
            __threadfence();
            int t = atomicAdd(&g_scan_ctr, 1);
            is_last = (t == SCAN_NB - 1);
        }
        __syncthreads();
        if (!is_last) return;
        int v = (tid < SCAN_NB) ? *(volatile int*)&g_partials[tid] : 0;
        sh[tid] = v;
        __syncthreads();
        for (int off = 1; off < 256; off <<= 1) {
            int t = (tid >= off) ? sh[tid - off] : 0;
            __syncthreads();
            sh[tid] += t;
            __syncthreads();
        }
        if (tid < SCAN_NB) g_partials[tid] = sh[tid] - v;
        __threadfence();
        __syncthreads();
        if (tid == 0) atomicExch(&g_scan_done, 1);
        return;
    }

    if (bid < SCAN_NB + gemm_blocks) {
        int gb = bid - SCAN_NB;
        int row0 = gb * 128;
        for (int i = tid; i < D * D; i += 256) Ws[i] = W[i];
        int tx = tid & 15, ty = tid >> 4;
        float acc[8][4] = {};

        for (int kb = 0; kb < D; kb += 32) {
            __syncthreads();
            for (int i = tid; i < 128 * 32; i += 256) {
                int rr = i >> 5, kk = i & 31;
                int r = row0 + rr;
                float v = (r < NN) ? A[(long long)r * D + kb + kk] : 0.f;
                As[kk * APAD + (rr ^ (((kk >> 3) & 3) << 3))] = v;
            }
            __syncthreads();
#pragma unroll
            for (int k = 0; k < 32; k++) {
                int tys = (ty ^ ((k >> 3) & 3)) * 8;
                float4 a0 = *(const float4*)&As[k * APAD + tys];
                float4 a1 = *(const float4*)&As[k * APAD + tys + 4];
                float4 wv = *(const float4*)&Ws[(kb + k) * D + tx * 4];
                float av[8] = {a0.x, a0.y, a0.z, a0.w, a1.x, a1.y, a1.z, a1.w};
#pragma unroll
                for (int i2 = 0; i2 < 8; i2++) {
                    acc[i2][0] += av[i2] * wv.x;
                    acc[i2][1] += av[i2] * wv.y;
                    acc[i2][2] += av[i2] * wv.z;
                    acc[i2][3] += av[i2] * wv.w;
                }
            }
        }
#pragma unroll
        for (int i2 = 0; i2 < 8; i2++) {
            int r = row0 + ty * 8 + i2;
            if (r >= NN) break;
            __half2 ha = __floats2half2_rn(acc[i2][0], acc[i2][1]);
            __half2 hb = __floats2half2_rn(acc[i2][2], acc[i2][3]);
            uint2 u;
            u.x = *(unsigned*)&ha;
            u.y = *(unsigned*)&hb;
            ((uint2*)hout)[(long long)r * 16 + tx] = u;
        }
        return;
    }

    if (tid == 0) {
        while (atomicAdd(&g_scan_done, 0) == 0) __nanosleep(64);
    }
    __syncthreads();
    {
        int base = (bid - SCAN_NB - gemm_blocks) * 1024 + tid;
        int is64 = g_is64_edge;
        int r[4], c[4]; float w[4];
#pragma unroll
        for (int j = 0; j < 4; j++) {
            int e = base + j * 256;
            if (e < EE) {
                r[j] = load_idx(ei, e, is64);
                c[j] = load_idx(ei, (long long)EE + e, is64);
                w[j] = ew[e];
            } else c[j] = -1;
        }
        float dr[4], dc[4]; int pp[4];
#pragma unroll
        for (int j = 0; j < 4; j++) {
            if (c[j] >= 0) {
                dr[j] = g_deg[r[j]];
                dc[j] = g_deg[c[j]];
                pp[j] = g_ptr[c[j]] + g_partials[c[j] >> 9];
            }
        }
#pragma unroll
        for (int j = 0; j < 4; j++) {
            if (c[j] >= 0) {
                float ir = dr[j] > 0.f ? rsqrtf(dr[j]) : 0.f;
                float ic = dc[j] > 0.f ? rsqrtf(dc[j]) : 0.f;
                int old = atomicSub(&g_cntn[c[j]], 1);
                g_csr[pp[j] + old - 1] = make_int2(r[j], __float_as_int(ir * w[j] * ic));
            }
        }
    }
}

// ---------------- CSR aggregation core: 4x unrolled, 16 edges in flight ------
__device__ __forceinline__ void agg_accum(float acc[8], uint4 u, float nv) {
    __half2* hh = (__half2*)&u;
#pragma unroll
    for (int c = 0; c < 4; c++) {
        float2 f = __half22float2(hh[c]);
        acc[2 * c]     += f.x * nv;
        acc[2 * c + 1] += f.y * nv;
    }
}

__device__ __forceinline__ void agg_core(int node, const uint4* __restrict__ h,
                                         int q, int p, float acc[8]) {
    int s = ptr_of(node), e = ptr_of(node + 1);
    int i = s + q;
    for (; i + 12 < e; i += 16) {
        int2 e0 = g_csr[i];
        int2 e1 = g_csr[i + 4];
        int2 e2 = g_csr[i + 8];
        int2 e3 = g_csr[i + 12];
        uint4 u0 = h[e0.x * 8 + p];
        uint4 u1 = h[e1.x * 8 + p];
        uint4 u2 = h[e2.x * 8 + p];
        uint4 u3 = h[e3.x * 8 + p];
        agg_accum(acc, u0, __int_as_float(e0.y));
        agg_accum(acc, u1, __int_as_float(e1.y));
        agg_accum(acc, u2, __int_as_float(e2.y));
        agg_accum(acc, u3, __int_as_float(e3.y));
    }
    if (i + 4 < e) {
        int2 e0 = g_csr[i];
        int2 e1 = g_csr[i + 4];
        uint4 u0 = h[e0.x * 8 + p];
        uint4 u1 = h[e1.x * 8 + p];
        agg_accum(acc, u0, __int_as_float(e0.y));
        agg_accum(acc, u1, __int_as_float(e1.y));
        i += 8;
    }
    if (i < e) {
        int2 e0 = g_csr[i];
        uint4 u0 = h[e0.x * 8 + p];
        agg_accum(acc, u0, __int_as_float(e0.y));
    }
#pragma unroll
    for (int c = 0; c < 8; c++) {
        acc[c] += __shfl_xor_sync(0xffffffffu, acc[c], 8);
        acc[c] += __shfl_xor_sync(0xffffffffu, acc[c], 16);
    }
}

__device__ __forceinline__ void red_add_v4(float4* addr, float4 v) {
    asm volatile("red.global.add.v4.f32 [%0], {%1,%2,%3,%4};"
                 :: "l"(addr), "f"(v.x), "f"(v.y), "f"(v.z), "f"(v.w)
                 : "memory");
}

// ---------------- conv chain: one launch for layers 1..3 + pool --------------
// Sections (by bid, producers strictly before consumers):
//   A1(12500) -> G2(1563) -> A2 -> G3 -> A3 -> G4 -> POOL(12500)
// agg blocks publish per-64-row-tile counters; gemm blocks spin on their OWN
// tile (fine-grained overlap); agg/pool blocks spin on full gemm-done scalars.
__global__ void __launch_bounds__(256, 6)
conv_chain(const float* __restrict__ conv_w, const float* __restrict__ conv_b,
           const void* batch) {
    __shared__ float Ws[D * D];       // 16 KB (gemm sections only)
    __shared__ float As[16 * GPAD];   // 4.5 KB
    int tid = threadIdx.x;
    int bid = blockIdx.x;

    int sec, blk = bid;
    if (blk < AGB) sec = 0;
    else if ((blk -= AGB) < GB2) sec = 1;
    else if ((blk -= GB2) < AGB) sec = 2;
    else if ((blk -= AGB) < GB2) sec = 3;
    else if ((blk -= GB2) < AGB) sec = 4;
    else if ((blk -= AGB) < GB2) sec = 5;
    else { blk -= GB2; sec = 6; }

    if (sec == 1 || sec == 3 || sec == 5) {
        // ================= gemm section: 64x64 tile, 2x8 per thread ==========
        int L = sec >> 1;                 // 0,1,2 -> weights conv_w[(L+1)]
        const float* A = (L == 0) ? g_aggA : (L == 1) ? g_aggB : g_aggC;
        unsigned* hout = (unsigned*)((L == 0) ? g_h2 : (L == 1) ? g_h3 : g_h4);
        const float* W = conv_w + (L + 1) * D * D;
        int expect = (blk < GB2 - 1) ? 8 : (AGB - (GB2 - 1) * 8);  // 8 or 4
        if (tid == 0) {
            while (atomicAdd(&g_tileCnt[L][blk], 0) < expect) __nanosleep(128);
        }
        __syncthreads();
        __threadfence();

        int row0 = blk * 64;
        for (int i = tid; i < D * D; i += 256) Ws[i] = W[i];
        int tx = tid & 7, ty = tid >> 3;  // 8 col groups x 32 row groups (2 rows)
        float acc[2][8] = {};

        for (int kb = 0; kb < D; kb += 16) {
            __syncthreads();
            for (int i = tid; i < 64 * 16; i += 256) {
                int rr = i >> 4, kk = i & 15;
                int r = row0 + rr;
                As[kk * GPAD + rr] = (r < NN) ? A[(long long)r * D + kb + kk] : 0.f;
            }
            __syncthreads();
#pragma unroll
            for (int k = 0; k < 16; k++) {
                float2 a = *(const float2*)&As[k * GPAD + ty * 2];
                float4 w0 = *(const float4*)&Ws[(kb + k) * D + tx * 8];
                float4 w1 = *(const float4*)&Ws[(kb + k) * D + tx * 8 + 4];
                float wv[8] = {w0.x, w0.y, w0.z, w0.w, w1.x, w1.y, w1.z, w1.w};
#pragma unroll
                for (int j = 0; j < 8; j++) {
                    acc[0][j] += a.x * wv[j];
                    acc[1][j] += a.y * wv[j];
                }
            }
        }
#pragma unroll
        for (int i2 = 0; i2 < 2; i2++) {
            int r = row0 + ty * 2 + i2;
            if (r >= NN) break;
            __half2 h0 = __floats2half2_rn(acc[i2][0], acc[i2][1]);
            __half2 h1 = __floats2half2_rn(acc[i2][2], acc[i2][3]);
            __half2 h2 = __floats2half2_rn(acc[i2][4], acc[i2][5]);
            __half2 h3 = __floats2half2_rn(acc[i2][6], acc[i2][7]);
            uint4 u;
            u.x = *(unsigned*)&h0;
            u.y = *(unsigned*)&h1;
            u.z = *(unsigned*)&h2;
            u.w = *(unsigned*)&h3;
            *(uint4*)&hout[(long long)r * 32 + tx * 4] = u;
        }
        __threadfence();
        __syncthreads();
        if (tid == 0) atomicAdd(&g_gemmDone[L], 1);
        return;
    }

    // ================= agg / pool sections ==================================
    int aidx = sec >> 1;  // 0..3 (3 = pool)
    const uint4* hin = (aidx == 0) ? g_h1 : (aidx == 1) ? g_h2
                       : (aidx == 2) ? g_h3 : g_h4;
    const float* bias = conv_b + aidx * D;
    if (aidx > 0) {  // wait for the producing gemm layer
        if (tid == 0) {
            while (atomicAdd(&g_gemmDone[aidx - 1], 0) < GB2) __nanosleep(128);
        }
        __syncthreads();
        __threadfence();
    }

    int node = (blk * 256 + tid) >> 5;
    int lane = tid & 31;
    int q = lane >> 3, p = lane & 7;
    float acc[8] = {};
    if (node < NN) agg_core(node, hin, q, p, acc);

    if (sec == 6) {
        // pool: relu + mean-pool accumulate
        if (node < NN && q == 0) {
            int g = load_idx(batch, node, g_is64_batch);
            float4 b0 = *(const float4*)&bias[8 * p];
            float4 b1 = *(const float4*)&bias[8 * p + 4];
            float4 o0 = make_float4(fmaxf(acc[0] + b0.x, 0.f), fmaxf(acc[1] + b0.y, 0.f),
                                    fmaxf(acc[2] + b0.z, 0.f), fmaxf(acc[3] + b0.w, 0.f));
            float4 o1 = make_float4(fmaxf(acc[4] + b1.x, 0.f), fmaxf(acc[5] + b1.y, 0.f),
                                    fmaxf(acc[6] + b1.z, 0.f), fmaxf(acc[7] + b1.w, 0.f));
            float* row = g_sums + g * D + 8 * p;
            red_add_v4((float4*)row, o0);
            red_add_v4((float4*)(row + 4), o1);
            if (p == 0) atomicAdd(&g_cnt[g], 1.0f);
        }
        return;
    }

    float* outp = (aidx == 0) ? g_aggA : (aidx == 1) ? g_aggB : g_aggC;
    if (node < NN && q == 0) {
        float4 b0 = *(const float4*)&bias[8 * p];
        float4 b1 = *(const float4*)&bias[8 * p + 4];
        float4 o0 = make_float4(fmaxf(acc[0] + b0.x, 0.f), fmaxf(acc[1] + b0.y, 0.f),
                                fmaxf(acc[2] + b0.z, 0.f), fmaxf(acc[3] + b0.w, 0.f));
        float4 o1 = make_float4(fmaxf(acc[4] + b1.x, 0.f), fmaxf(acc[5] + b1.y, 0.f),
                                fmaxf(acc[6] + b1.z, 0.f), fmaxf(acc[7] + b1.w, 0.f));
        float* row = outp + (long long)node * D + 8 * p;
        *(float4*)row = o0;
        *(float4*)(row + 4) = o1;
    }
    __threadfence();
    __syncthreads();
    if (tid == 0) atomicAdd(&g_tileCnt[aidx][blk >> 3], 1);  // 8 agg blocks/tile
}

// ---------------- fused MLP tail: lin1 -> fc0 -> fc1 -> lin2 ----------------
__global__ void tail_kernel(const float* __restrict__ W1, const float* __restrict__ b1,
                            const float* __restrict__ fcw, const float* __restrict__ fcb,
                            const float* __restrict__ w2, const float* __restrict__ b2,
                            float* __restrict__ out) {
    int g = blockIdx.x, tid = threadIdx.x;  // 64 threads
    __shared__ float buf[2][64];
    __shared__ float red[64];

    buf[0][tid] = g_sums[g * D + tid] / fmaxf(g_cnt[g], 1.f);
    __syncthreads();
    {
        float acc = 0.f;
#pragma unroll
        for (int k = 0; k < 64; k++) acc += buf[0][k] * W1[k * D + tid];
        buf[1][tid] = fmaxf(acc + b1[tid], 0.f);
        __syncthreads();
    }
    int cur = 1;
    for (int L = 0; L < 2; L++) {
        const float* W = fcw + L * D * D;
        float acc = 0.f;
#pragma unroll
        for (int k = 0; k < 64; k++) acc += buf[cur][k] * W[k * D + tid];
        __syncthreads();
        buf[cur ^ 1][tid] = fmaxf(acc + fcb[L * D + tid], 0.f);
        cur ^= 1;
        __syncthreads();
    }
    red[tid] = buf[cur][tid] * w2[tid];
    __syncthreads();
    if (tid < 32) {
        float s = red[tid] + red[tid + 32];
#pragma unroll
        for (int off = 16; off; off >>= 1) s += __shfl_down_sync(0xffffffffu, s, off);
        if (tid == 0) out[g] = s + b2[0];
    }
}

// ---------------- launch ----------------
extern "C" void kernel_launch(void* const* d_in, const int* in_sizes, int n_in,
                              void* d_out, int out_size) {
    const float* x      = (const float*)d_in[0];
    const void*  ei     = d_in[1];
    const float* ew     = (const float*)d_in[2];
    const void*  batch  = d_in[3];
    const float* lin0_w = (const float*)d_in[4];
    const float* lin0_b = (const float*)d_in[5];
    const float* conv_w = (const float*)d_in[6];
    const float* conv_b = (const float*)d_in[7];
    const float* lin1_w = (const float*)d_in[8];
    const float* lin1_b = (const float*)d_in[9];
    const float* fc_w   = (const float*)d_in[10];
    const float* fc_b   = (const float*)d_in[11];
    const float* lin2_w = (const float*)d_in[12];
    const float* lin2_b = (const float*)d_in[13];
    float* out = (float*)d_out;

    float* p_out0;
    uint4* p_h1;
    cudaGetSymbolAddress((void**)&p_out0, g_out0);
    cudaGetSymbolAddress((void**)&p_h1, g_h1);

    // init: zero deg/cntn/sums/cnt/flags/counters + dtype detect
    init_kernel<<<(NN + 255) / 256, 256>>>((const int*)ei, (const int*)batch);

    // fused lin0 GEMM + degree histogram (overlapped, 4 edges/thread)
    const int GB = (NN + 127) / 128;            // 782 gemm blocks (128-row)
    const int DB4 = (EE + 1023) / 1024;         // 1563 edge blocks
    fused_lin0_deg<<<GB + DB4, 256>>>(x, lin0_w, lin0_b, p_out0, ei, ew, GB);

    // mega: scan (196) | conv-0 GEMM (782) | scatter (1563) — one launch
    mega_conv0<<<SCAN_NB + GB + DB4, 256>>>(p_out0, conv_w, (unsigned*)p_h1, ei, ew, GB);

    // conv chain: layers 1..3 + pool — one launch, pipelined sections
    conv_chain<<<4 * AGB + 3 * GB2, 256>>>(conv_w, conv_b, batch);

    tail_kernel<<<GG, 64>>>(lin1_w, lin1_b, fc_w, fc_b, lin2_w, lin2_b, out);
}

// round 15
// speedup vs baseline: 1.6257x; 1.6257x over previous
#include <cuda_runtime.h>
#include <cuda_fp16.h>

#define NN 100000
#define EE 1600000
#define FIN 100
#define D 64
#define GG 500
#define SCAN_T 512
#define SCAN_NB ((NN + SCAN_T - 1) / SCAN_T)
#define APAD 132

// ---------------- scratch (device globals; no allocs allowed) ----------------
__device__ float g_deg[NN];
__device__ int   g_cntn[NN];
__device__ int   g_ptr[NN + 1];
__device__ int   g_partials[SCAN_NB];
__device__ int2  g_csr[EE];        // packed {row, norm_bits}
__device__ uint4 g_out0[NN * 8];   // lin0 out, fp16 (64 halves = 8 uint4/row)
__device__ uint4 g_hh[NN * 8];     // h fp16
__device__ uint4 g_aggA[NN * 8];   // agg out ping, fp16
__device__ uint4 g_aggB[NN * 8];   // agg out pong, fp16
__device__ float g_sums[GG * D];
__device__ float g_cnt[GG];
__device__ int g_is64_edge;
__device__ int g_is64_batch;
__device__ int g_scan_ctr;
__device__ int g_scan_done;

__device__ __forceinline__ int load_idx(const void* p, long long i, int is64) {
    return is64 ? (int)((const long long*)p)[i] : ((const int*)p)[i];
}

// ptr fixup inlined: final ptr(n) = g_ptr[n] + partials[n>>9]
__device__ __forceinline__ int ptr_of(int n) {
    return (n == NN) ? EE : g_ptr[n] + g_partials[n >> 9];
}

// ---------------- init: zero scratch + dtype detect (one kernel) -------------
__global__ void init_kernel(const int* ei, const int* bat) {
    int t = blockIdx.x * 256 + threadIdx.x;
    if (t < NN) { g_deg[t] = 0.f; g_cntn[t] = 0; }
    if (t < GG * D) g_sums[t] = 0.f;
    if (t < GG) g_cnt[t] = 0.f;
    if (t == 0) { g_scan_ctr = 0; g_scan_done = 0; }
    if (blockIdx.x == 0 && threadIdx.x < 32) {
        int i = threadIdx.x;
        int nz_e = 0, nz_b = 0;
        for (int j = i; j < 128; j += 32) {
            int w = 1 + 700 * j;  // always odd, < NN words
            nz_e |= (ei[w] != 0);
            nz_b |= (bat[w] != 0);
        }
        unsigned be = __ballot_sync(0xffffffffu, nz_e);
        unsigned bb = __ballot_sync(0xffffffffu, nz_b);
        if (i == 0) {
            g_is64_edge = (be == 0);
            g_is64_batch = (bb == 0);
        }
    }
}

// ---------------- fused: lin0 GEMM (fp32 math, fp16 out) + degree histogram --
__global__ void fused_lin0_deg(const float* __restrict__ A, const float* __restrict__ W,
                               const float* __restrict__ biasC, unsigned* __restrict__ C,
                               const void* ei, const float* __restrict__ ew,
                               int gemm_blocks) {
    __shared__ float Ws[FIN * D];
    __shared__ float As[20 * APAD];
    int tid = threadIdx.x;

    if (blockIdx.x >= gemm_blocks) {
        int base = (blockIdx.x - gemm_blocks) * 1024 + tid;
        int is64 = g_is64_edge;
        int c[4]; float w[4];
#pragma unroll
        for (int j = 0; j < 4; j++) {
            int e = base + j * 256;
            if (e < EE) {
                c[j] = load_idx(ei, (long long)EE + e, is64);
                w[j] = ew[e];
            } else c[j] = -1;
        }
#pragma unroll
        for (int j = 0; j < 4; j++) {
            if (c[j] >= 0) {
                atomicAdd(&g_deg[c[j]], w[j]);
                atomicAdd(&g_cntn[c[j]], 1);
            }
        }
        return;
    }

    int row0 = blockIdx.x * 128;
    for (int i = tid; i < FIN * D; i += 256) Ws[i] = W[i];
    int tx = tid & 15, ty = tid >> 4;
    float acc[8][4] = {};

    for (int kb = 0; kb < FIN; kb += 20) {
        __syncthreads();  // also guards Ws on first iteration
        for (int i = tid; i < 128 * 20; i += 256) {
            int rr = i / 20, kk = i - rr * 20;
            int r = row0 + rr;
            As[kk * APAD + rr] = (r < NN) ? A[(long long)r * FIN + kb + kk] : 0.f;
        }
        __syncthreads();
#pragma unroll
        for (int k = 0; k < 20; k++) {
            float4 a0 = *(const float4*)&As[k * APAD + ty * 8];
            float4 a1 = *(const float4*)&As[k * APAD + ty * 8 + 4];
            float4 wv = *(const float4*)&Ws[(kb + k) * D + tx * 4];
            float av[8] = {a0.x, a0.y, a0.z, a0.w, a1.x, a1.y, a1.z, a1.w};
#pragma unroll
            for (int i2 = 0; i2 < 8; i2++) {
                acc[i2][0] += av[i2] * wv.x;
                acc[i2][1] += av[i2] * wv.y;
                acc[i2][2] += av[i2] * wv.z;
                acc[i2][3] += av[i2] * wv.w;
            }
        }
    }
    int c0 = tx * 4;
    float4 bc = *(const float4*)&biasC[c0];
#pragma unroll
    for (int i2 = 0; i2 < 8; i2++) {
        int r = row0 + ty * 8 + i2;
        if (r >= NN) break;
        float4 v = make_float4(fmaxf(acc[i2][0] + bc.x, 0.f), fmaxf(acc[i2][1] + bc.y, 0.f),
                               fmaxf(acc[i2][2] + bc.z, 0.f), fmaxf(acc[i2][3] + bc.w, 0.f));
        __half2 ha = __floats2half2_rn(v.x, v.y);
        __half2 hb = __floats2half2_rn(v.z, v.w);
        uint2 u;
        u.x = *(unsigned*)&ha;
        u.y = *(unsigned*)&hb;
        ((uint2*)C)[(long long)r * 16 + tx] = u;
    }
}

// ---------------- fp16 A staging helper (128 rows x 32 k chunk) --------------
__device__ __forceinline__ void stage_half_tile(float* As, const __half* Ah,
                                                int row0, int kb, int nrows, int tid) {
    for (int i = tid; i < 128 * 16; i += 256) {
        int rr = i >> 4, kp = i & 15;
        int r = row0 + rr;
        float2 v = make_float2(0.f, 0.f);
        if (r < nrows)
            v = __half22float2(*(const __half2*)(Ah + (long long)r * 64 + kb + 2 * kp));
        int k0 = 2 * kp;
        int sw = rr ^ (((k0 >> 3) & 3) << 3);  // k0,k0+1 share (k>>3)
        As[k0 * APAD + sw] = v.x;
        As[(k0 + 1) * APAD + sw] = v.y;
    }
}

// ---------------- mega kernel: [scan | conv0 GEMM | scatter] -----------------
__global__ void mega_conv0(const uint4* __restrict__ A, const float* __restrict__ W,
                           unsigned* __restrict__ hout,
                           const void* ei, const float* __restrict__ ew,
                           int gemm_blocks) {
    __shared__ float Ws[D * D];
    __shared__ float As[32 * APAD];
    __shared__ int sh[256];
    __shared__ int is_last;
    int tid = threadIdx.x;
    int bid = blockIdx.x;

    if (bid < SCAN_NB) {
        int i0 = bid * SCAN_T + 2 * tid;
        int a = (i0 < NN) ? g_cntn[i0] : 0;
        int b = (i0 + 1 < NN) ? g_cntn[i0 + 1] : 0;
        sh[tid] = a + b;
        __syncthreads();
        for (int off = 1; off < 256; off <<= 1) {
            int t = (tid >= off) ? sh[tid - off] : 0;
            __syncthreads();
            sh[tid] += t;
            __syncthreads();
        }
        int excl = sh[tid] - (a + b);
        if (i0 < NN) g_ptr[i0] = excl;
        if (i0 + 1 < NN) g_ptr[i0 + 1] = excl + a;
        if (tid == 255) {
            g_partials[bid] = sh[255];
            __threadfence();
            int t = atomicAdd(&g_scan_ctr, 1);
            is_last = (t == SCAN_NB - 1);
        }
        __syncthreads();
        if (!is_last) return;
        int v = (tid < SCAN_NB) ? *(volatile int*)&g_partials[tid] : 0;
        sh[tid] = v;
        __syncthreads();
        for (int off = 1; off < 256; off <<= 1) {
            int t = (tid >= off) ? sh[tid - off] : 0;
            __syncthreads();
            sh[tid] += t;
            __syncthreads();
        }
        if (tid < SCAN_NB) g_partials[tid] = sh[tid] - v;
        __threadfence();
        __syncthreads();
        if (tid == 0) atomicExch(&g_scan_done, 1);
        return;
    }

    if (bid < SCAN_NB + gemm_blocks) {
        int gb = bid - SCAN_NB;
        int row0 = gb * 128;
        for (int i = tid; i < D * D; i += 256) Ws[i] = W[i];
        int tx = tid & 15, ty = tid >> 4;
        float acc[8][4] = {};

        for (int kb = 0; kb < D; kb += 32) {
            __syncthreads();
            stage_half_tile(As, (const __half*)A, row0, kb, NN, tid);
            __syncthreads();
#pragma unroll
            for (int k = 0; k < 32; k++) {
                int tys = (ty ^ ((k >> 3) & 3)) * 8;
                float4 a0 = *(const float4*)&As[k * APAD + tys];
                float4 a1 = *(const float4*)&As[k * APAD + tys + 4];
                float4 wv = *(const float4*)&Ws[(kb + k) * D + tx * 4];
                float av[8] = {a0.x, a0.y, a0.z, a0.w, a1.x, a1.y, a1.z, a1.w};
#pragma unroll
                for (int i2 = 0; i2 < 8; i2++) {
                    acc[i2][0] += av[i2] * wv.x;
                    acc[i2][1] += av[i2] * wv.y;
                    acc[i2][2] += av[i2] * wv.z;
                    acc[i2][3] += av[i2] * wv.w;
                }
            }
        }
#pragma unroll
        for (int i2 = 0; i2 < 8; i2++) {
            int r = row0 + ty * 8 + i2;
            if (r >= NN) break;
            __half2 ha = __floats2half2_rn(acc[i2][0], acc[i2][1]);
            __half2 hb = __floats2half2_rn(acc[i2][2], acc[i2][3]);
            uint2 u;
            u.x = *(unsigned*)&ha;
            u.y = *(unsigned*)&hb;
            ((uint2*)hout)[(long long)r * 16 + tx] = u;
        }
        return;
    }

    if (tid == 0) {
        while (atomicAdd(&g_scan_done, 0) == 0) __nanosleep(64);
    }
    __syncthreads();
    {
        int base = (bid - SCAN_NB - gemm_blocks) * 1024 + tid;
        int is64 = g_is64_edge;
        int r[4], c[4]; float w[4];
#pragma unroll
        for (int j = 0; j < 4; j++) {
            int e = base + j * 256;
            if (e < EE) {
                r[j] = load_idx(ei, e, is64);
                c[j] = load_idx(ei, (long long)EE + e, is64);
                w[j] = ew[e];
            } else c[j] = -1;
        }
        float dr[4], dc[4]; int pp[4];
#pragma unroll
        for (int j = 0; j < 4; j++) {
            if (c[j] >= 0) {
                dr[j] = g_deg[r[j]];
                dc[j] = g_deg[c[j]];
                pp[j] = g_ptr[c[j]] + g_partials[c[j] >> 9];
            }
        }
#pragma unroll
        for (int j = 0; j < 4; j++) {
            if (c[j] >= 0) {
                float ir = dr[j] > 0.f ? rsqrtf(dr[j]) : 0.f;
                float ic = dc[j] > 0.f ? rsqrtf(dc[j]) : 0.f;
                int old = atomicSub(&g_cntn[c[j]], 1);
                g_csr[pp[j] + old - 1] = make_int2(r[j], __float_as_int(ir * w[j] * ic));
            }
        }
    }
}

// ---------------- conv GEMM layers 1..3 (fp16 in, fp32 math, fp16 out) -------
__global__ void gemm_conv(const uint4* __restrict__ A, const float* __restrict__ W,
                          unsigned* __restrict__ hout, int nrows) {
    __shared__ float Ws[D * D];
    __shared__ float As[32 * APAD];

    int tid = threadIdx.x;
    int row0 = blockIdx.x * 128;
    for (int i = tid; i < D * D; i += 256) Ws[i] = W[i];
    int tx = tid & 15, ty = tid >> 4;
    float acc[8][4] = {};

    for (int kb = 0; kb < D; kb += 32) {
        __syncthreads();
        stage_half_tile(As, (const __half*)A, row0, kb, nrows, tid);
        __syncthreads();
#pragma unroll
        for (int k = 0; k < 32; k++) {
            int tys = (ty ^ ((k >> 3) & 3)) * 8;
            float4 a0 = *(const float4*)&As[k * APAD + tys];
            float4 a1 = *(const float4*)&As[k * APAD + tys + 4];
            float4 wv = *(const float4*)&Ws[(kb + k) * D + tx * 4];
            float av[8] = {a0.x, a0.y, a0.z, a0.w, a1.x, a1.y, a1.z, a1.w};
#pragma unroll
            for (int i2 = 0; i2 < 8; i2++) {
                acc[i2][0] += av[i2] * wv.x;
                acc[i2][1] += av[i2] * wv.y;
                acc[i2][2] += av[i2] * wv.z;
                acc[i2][3] += av[i2] * wv.w;
            }
        }
    }

#pragma unroll
    for (int i2 = 0; i2 < 8; i2++) {
        int r = row0 + ty * 8 + i2;
        if (r >= nrows) break;
        __half2 ha = __floats2half2_rn(acc[i2][0], acc[i2][1]);
        __half2 hb = __floats2half2_rn(acc[i2][2], acc[i2][3]);
        uint2 u;
        u.x = *(unsigned*)&ha;
        u.y = *(unsigned*)&hb;
        ((uint2*)hout)[(long long)r * 16 + tx] = u;
    }
}

// ---------------- CSR aggregation core: 4x unrolled, 16 edges in flight ------
__device__ __forceinline__ void agg_accum(float acc[8], uint4 u, float nv) {
    __half2* hh = (__half2*)&u;
#pragma unroll
    for (int c = 0; c < 4; c++) {
        float2 f = __half22float2(hh[c]);
        acc[2 * c]     += f.x * nv;
        acc[2 * c + 1] += f.y * nv;
    }
}

__device__ __forceinline__ void agg_core(int node, const uint4* __restrict__ h,
                                         int q, int p, float acc[8]) {
    int s = ptr_of(node), e = ptr_of(node + 1);
    int i = s + q;
    for (; i + 12 < e; i += 16) {
        int2 e0 = g_csr[i];
        int2 e1 = g_csr[i + 4];
        int2 e2 = g_csr[i + 8];
        int2 e3 = g_csr[i + 12];
        uint4 u0 = h[e0.x * 8 + p];
        uint4 u1 = h[e1.x * 8 + p];
        uint4 u2 = h[e2.x * 8 + p];
        uint4 u3 = h[e3.x * 8 + p];
        agg_accum(acc, u0, __int_as_float(e0.y));
        agg_accum(acc, u1, __int_as_float(e1.y));
        agg_accum(acc, u2, __int_as_float(e2.y));
        agg_accum(acc, u3, __int_as_float(e3.y));
    }
    if (i + 4 < e) {
        int2 e0 = g_csr[i];
        int2 e1 = g_csr[i + 4];
        uint4 u0 = h[e0.x * 8 + p];
        uint4 u1 = h[e1.x * 8 + p];
        agg_accum(acc, u0, __int_as_float(e0.y));
        agg_accum(acc, u1, __int_as_float(e1.y));
        i += 8;
    }
    if (i < e) {
        int2 e0 = g_csr[i];
        uint4 u0 = h[e0.x * 8 + p];
        agg_accum(acc, u0, __int_as_float(e0.y));
    }
#pragma unroll
    for (int c = 0; c < 8; c++) {
        acc[c] += __shfl_xor_sync(0xffffffffu, acc[c], 8);
        acc[c] += __shfl_xor_sync(0xffffffffu, acc[c], 16);
    }
}

// agg with fp16 output row (uint4 per lane p)
__global__ void agg_half(const uint4* __restrict__ h,
                         const float* __restrict__ bias, uint4* __restrict__ outp) {
    int node = (blockIdx.x * blockDim.x + threadIdx.x) >> 5;
    if (node >= NN) return;
    int lane = threadIdx.x & 31;
    int q = lane >> 3, p = lane & 7;
    float acc[8] = {};
    agg_core(node, h, q, p, acc);
    if (q == 0) {
        float4 b0 = *(const float4*)&bias[8 * p];
        float4 b1 = *(const float4*)&bias[8 * p + 4];
        float o[8];
        o[0] = fmaxf(acc[0] + b0.x, 0.f); o[1] = fmaxf(acc[1] + b0.y, 0.f);
        o[2] = fmaxf(acc[2] + b0.z, 0.f); o[3] = fmaxf(acc[3] + b0.w, 0.f);
        o[4] = fmaxf(acc[4] + b1.x, 0.f); o[5] = fmaxf(acc[5] + b1.y, 0.f);
        o[6] = fmaxf(acc[6] + b1.z, 0.f); o[7] = fmaxf(acc[7] + b1.w, 0.f);
        __half2 h0 = __floats2half2_rn(o[0], o[1]);
        __half2 h1 = __floats2half2_rn(o[2], o[3]);
        __half2 h2 = __floats2half2_rn(o[4], o[5]);
        __half2 h3 = __floats2half2_rn(o[6], o[7]);
        uint4 u;
        u.x = *(unsigned*)&h0;
        u.y = *(unsigned*)&h1;
        u.z = *(unsigned*)&h2;
        u.w = *(unsigned*)&h3;
        outp[node * 8 + p] = u;
    }
}

__device__ __forceinline__ void red_add_v4(float4* addr, float4 v) {
    asm volatile("red.global.add.v4.f32 [%0], {%1,%2,%3,%4};"
                 :: "l"(addr), "f"(v.x), "f"(v.y), "f"(v.z), "f"(v.w)
                 : "memory");
}

// Last layer: aggregate + bias + relu + mean-pool accumulate (fp32 path).
__global__ void agg_pool(const uint4* __restrict__ h,
                         const float* __restrict__ bias, const void* batch) {
    int node = (blockIdx.x * blockDim.x + threadIdx.x) >> 5;
    if (node >= NN) return;
    int lane = threadIdx.x & 31;
    int q = lane >> 3, p = lane & 7;
    float acc[8] = {};
    agg_core(node, h, q, p, acc);
    if (q == 0) {
        int g = load_idx(batch, node, g_is64_batch);
        float4 b0 = *(const float4*)&bias[8 * p];
        float4 b1 = *(const float4*)&bias[8 * p + 4];
        float4 o0 = make_float4(fmaxf(acc[0] + b0.x, 0.f), fmaxf(acc[1] + b0.y, 0.f),
                                fmaxf(acc[2] + b0.z, 0.f), fmaxf(acc[3] + b0.w, 0.f));
        float4 o1 = make_float4(fmaxf(acc[4] + b1.x, 0.f), fmaxf(acc[5] + b1.y, 0.f),
                                fmaxf(acc[6] + b1.z, 0.f), fmaxf(acc[7] + b1.w, 0.f));
        float* row = g_sums + g * D + 8 * p;
        red_add_v4((float4*)row, o0);
        red_add_v4((float4*)(row + 4), o1);
        if (p == 0) atomicAdd(&g_cnt[g], 1.0f);
    }
}

// ---------------- fused MLP tail: lin1 -> fc0 -> fc1 -> lin2 ----------------
__global__ void tail_kernel(const float* __restrict__ W1, const float* __restrict__ b1,
                            const float* __restrict__ fcw, const float* __restrict__ fcb,
                            const float* __restrict__ w2, const float* __restrict__ b2,
                            float* __restrict__ out) {
    int g = blockIdx.x, tid = threadIdx.x;  // 64 threads
    __shared__ float buf[2][64];
    __shared__ float red[64];

    buf[0][tid] = g_sums[g * D + tid] / fmaxf(g_cnt[g], 1.f);
    __syncthreads();
    {
        float acc = 0.f;
#pragma unroll
        for (int k = 0; k < 64; k++) acc += buf[0][k] * W1[k * D + tid];
        buf[1][tid] = fmaxf(acc + b1[tid], 0.f);
        __syncthreads();
    }
    int cur = 1;
    for (int L = 0; L < 2; L++) {
        const float* W = fcw + L * D * D;
        float acc = 0.f;
#pragma unroll
        for (int k = 0; k < 64; k++) acc += buf[cur][k] * W[k * D + tid];
        __syncthreads();
        buf[cur ^ 1][tid] = fmaxf(acc + fcb[L * D + tid], 0.f);
        cur ^= 1;
        __syncthreads();
    }
    red[tid] = buf[cur][tid] * w2[tid];
    __syncthreads();
    if (tid < 32) {
        float s = red[tid] + red[tid + 32];
#pragma unroll
        for (int off = 16; off; off >>= 1) s += __shfl_down_sync(0xffffffffu, s, off);
        if (tid == 0) out[g] = s + b2[0];
    }
}

// ---------------- launch ----------------
extern "C" void kernel_launch(void* const* d_in, const int* in_sizes, int n_in,
                              void* d_out, int out_size) {
    const float* x      = (const float*)d_in[0];
    const void*  ei     = d_in[1];
    const float* ew     = (const float*)d_in[2];
    const void*  batch  = d_in[3];
    const float* lin0_w = (const float*)d_in[4];
    const float* lin0_b = (const float*)d_in[5];
    const float* conv_w = (const float*)d_in[6];
    const float* conv_b = (const float*)d_in[7];
    const float* lin1_w = (const float*)d_in[8];
    const float* lin1_b = (const float*)d_in[9];
    const float* fc_w   = (const float*)d_in[10];
    const float* fc_b   = (const float*)d_in[11];
    const float* lin2_w = (const float*)d_in[12];
    const float* lin2_b = (const float*)d_in[13];
    float* out = (float*)d_out;

    uint4 *p_out0, *p_h, *p_aggA, *p_aggB;
    cudaGetSymbolAddress((void**)&p_out0, g_out0);
    cudaGetSymbolAddress((void**)&p_h,    g_hh);
    cudaGetSymbolAddress((void**)&p_aggA, g_aggA);
    cudaGetSymbolAddress((void**)&p_aggB, g_aggB);

    // init: zero deg/cntn/sums/cnt/scan flags + dtype detect
    init_kernel<<<(NN + 255) / 256, 256>>>((const int*)ei, (const int*)batch);

    // fused lin0 GEMM (fp16 out) + degree histogram (overlapped, 4 edges/thread)
    const int GB = (NN + 127) / 128;            // 782 gemm blocks
    const int DB4 = (EE + 1023) / 1024;         // 1563 edge blocks
    fused_lin0_deg<<<GB + DB4, 256>>>(x, lin0_w, lin0_b, (unsigned*)p_out0, ei, ew, GB);

    // mega: scan (196) | conv-0 GEMM (782) | scatter (1563) — one launch
    mega_conv0<<<SCAN_NB + GB + DB4, 256>>>(p_out0, conv_w, (unsigned*)p_h, ei, ew, GB);

    uint4* bufs[2] = {p_aggA, p_aggB};
    const int AGB = (NN * 32) / 256;  // 12500 blocks
    const uint4* Ain = nullptr;
    for (int i = 0; i < 4; i++) {
        if (i > 0) {
            gemm_conv<<<GB, 256>>>(Ain, conv_w + i * D * D, (unsigned*)p_h, NN);
        }
        if (i < 3) {
            uint4* agg = bufs[i & 1];
            agg_half<<<AGB, 256>>>(p_h, conv_b + i * D, agg);
            Ain = agg;
        } else {
            agg_pool<<<AGB, 256>>>(p_h, conv_b + i * D, batch);
        }
    }

    tail_kernel<<<GG, 64>>>(lin1_w, lin1_b, fc_w, fc_b, lin2_w, lin2_b, out);
}

// round 16
// speedup vs baseline: 1.7933x; 1.1031x over previous
#include <cuda_runtime.h>
#include <cuda_fp16.h>

#define NN 100000
#define EE 1600000
#define FIN 100
#define D 64
#define GG 500
#define SCAN_T 512
#define SCAN_NB ((NN + SCAN_T - 1) / SCAN_T)
#define APAD 132
#define HSTR 72   // half stride for mma smem tiles (144B rows -> ldmatrix conflict-free)

// ---------------- scratch (device globals; no allocs allowed) ----------------
__device__ float g_deg[NN];
__device__ int   g_cntn[NN];
__device__ int   g_ptr[NN + 1];
__device__ int   g_partials[SCAN_NB];
__device__ int2  g_csr[EE];        // packed {row, norm_bits}
__device__ uint4 g_out0[NN * 8];   // lin0 out, fp16 (64 halves = 8 uint4/row)
__device__ uint4 g_hh[NN * 8];     // h fp16
__device__ uint4 g_aggA[NN * 8];   // agg out ping, fp16
__device__ uint4 g_aggB[NN * 8];   // agg out pong, fp16
__device__ float g_sums[GG * D];
__device__ float g_cnt[GG];
__device__ int g_is64_edge;
__device__ int g_is64_batch;
__device__ int g_scan_ctr;
__device__ int g_scan_done;

__device__ __forceinline__ int load_idx(const void* p, long long i, int is64) {
    return is64 ? (int)((const long long*)p)[i] : ((const int*)p)[i];
}

// ptr fixup inlined: final ptr(n) = g_ptr[n] + partials[n>>9]
__device__ __forceinline__ int ptr_of(int n) {
    return (n == NN) ? EE : g_ptr[n] + g_partials[n >> 9];
}

// ---------------- init: zero scratch + dtype detect (one kernel) -------------
__global__ void init_kernel(const int* ei, const int* bat) {
    int t = blockIdx.x * 256 + threadIdx.x;
    if (t < NN) { g_deg[t] = 0.f; g_cntn[t] = 0; }
    if (t < GG * D) g_sums[t] = 0.f;
    if (t < GG) g_cnt[t] = 0.f;
    if (t == 0) { g_scan_ctr = 0; g_scan_done = 0; }
    if (blockIdx.x == 0 && threadIdx.x < 32) {
        int i = threadIdx.x;
        int nz_e = 0, nz_b = 0;
        for (int j = i; j < 128; j += 32) {
            int w = 1 + 700 * j;  // always odd, < NN words
            nz_e |= (ei[w] != 0);
            nz_b |= (bat[w] != 0);
        }
        unsigned be = __ballot_sync(0xffffffffu, nz_e);
        unsigned bb = __ballot_sync(0xffffffffu, nz_b);
        if (i == 0) {
            g_is64_edge = (be == 0);
            g_is64_batch = (bb == 0);
        }
    }
}

// ---------------- fused: lin0 GEMM (fp32 math, fp16 out) + degree histogram --
__global__ void fused_lin0_deg(const float* __restrict__ A, const float* __restrict__ W,
                               const float* __restrict__ biasC, unsigned* __restrict__ C,
                               const void* ei, const float* __restrict__ ew,
                               int gemm_blocks) {
    __shared__ float Ws[FIN * D];
    __shared__ float As[20 * APAD];
    int tid = threadIdx.x;

    if (blockIdx.x >= gemm_blocks) {
        int base = (blockIdx.x - gemm_blocks) * 1024 + tid;
        int is64 = g_is64_edge;
        int c[4]; float w[4];
#pragma unroll
        for (int j = 0; j < 4; j++) {
            int e = base + j * 256;
            if (e < EE) {
                c[j] = load_idx(ei, (long long)EE + e, is64);
                w[j] = ew[e];
            } else c[j] = -1;
        }
#pragma unroll
        for (int j = 0; j < 4; j++) {
            if (c[j] >= 0) {
                atomicAdd(&g_deg[c[j]], w[j]);
                atomicAdd(&g_cntn[c[j]], 1);
            }
        }
        return;
    }

    int row0 = blockIdx.x * 128;
    for (int i = tid; i < FIN * D; i += 256) Ws[i] = W[i];
    int tx = tid & 15, ty = tid >> 4;
    float acc[8][4] = {};

    for (int kb = 0; kb < FIN; kb += 20) {
        __syncthreads();  // also guards Ws on first iteration
        for (int i = tid; i < 128 * 20; i += 256) {
            int rr = i / 20, kk = i - rr * 20;
            int r = row0 + rr;
            As[kk * APAD + rr] = (r < NN) ? A[(long long)r * FIN + kb + kk] : 0.f;
        }
        __syncthreads();
#pragma unroll
        for (int k = 0; k < 20; k++) {
            float4 a0 = *(const float4*)&As[k * APAD + ty * 8];
            float4 a1 = *(const float4*)&As[k * APAD + ty * 8 + 4];
            float4 wv = *(const float4*)&Ws[(kb + k) * D + tx * 4];
            float av[8] = {a0.x, a0.y, a0.z, a0.w, a1.x, a1.y, a1.z, a1.w};
#pragma unroll
            for (int i2 = 0; i2 < 8; i2++) {
                acc[i2][0] += av[i2] * wv.x;
                acc[i2][1] += av[i2] * wv.y;
                acc[i2][2] += av[i2] * wv.z;
                acc[i2][3] += av[i2] * wv.w;
            }
        }
    }
    int c0 = tx * 4;
    float4 bc = *(const float4*)&biasC[c0];
#pragma unroll
    for (int i2 = 0; i2 < 8; i2++) {
        int r = row0 + ty * 8 + i2;
        if (r >= NN) break;
        float4 v = make_float4(fmaxf(acc[i2][0] + bc.x, 0.f), fmaxf(acc[i2][1] + bc.y, 0.f),
                               fmaxf(acc[i2][2] + bc.z, 0.f), fmaxf(acc[i2][3] + bc.w, 0.f));
        __half2 ha = __floats2half2_rn(v.x, v.y);
        __half2 hb = __floats2half2_rn(v.z, v.w);
        uint2 u;
        u.x = *(unsigned*)&ha;
        u.y = *(unsigned*)&hb;
        ((uint2*)C)[(long long)r * 16 + tx] = u;
    }
}

// ---------------- mma conv GEMM tile: h_out[128,64] = A[128,64]h @ W[64,64] --
// A fp16 in gmem; W fp32 split exactly into Whi + Wlo (both fp16) -> two
// fp32-accumulated mma chains; no precision loss beyond existing fp16 A.
// ldmatrix fragments; smem stride HSTR=72 halves (conflict-free).
__device__ __forceinline__ void mma_gemm_tile(
    const uint4* __restrict__ A, const float* __restrict__ W,
    unsigned* __restrict__ hout, int row0, int nrows,
    __half* As_h, __half* Wt0, __half* Wt1, int tid) {
    // stage W split (transposed: Wt[n][k])
    for (int i = tid; i < D * D; i += 256) {
        int k = i >> 6, n = i & 63;
        float w = W[i];
        __half hi = __float2half_rn(w);
        float res = w - __half2float(hi);
        Wt0[n * HSTR + k] = hi;
        Wt1[n * HSTR + k] = __float2half_rn(res);
    }
    // stage A tile: 128 rows x 64 halves
    for (int i = tid; i < 128 * 8; i += 256) {
        int r = i >> 3, c8 = i & 7;
        int gr = row0 + r;
        uint4 v = make_uint4(0u, 0u, 0u, 0u);
        if (gr < nrows) v = A[(long long)gr * 8 + c8];
        *(uint4*)&As_h[r * HSTR + c8 * 8] = v;
    }
    __syncthreads();

    int wid = tid >> 5, lane = tid & 31;
    int r0 = wid * 16;
    float d[8][4] = {};
    int aj = lane >> 3, ari = lane & 7;
    int l15 = lane & 15;
    int bj = l15 >> 3, bri = l15 & 7;

#pragma unroll
    for (int kc = 0; kc < 4; kc++) {
        int k0 = kc * 16;
        unsigned a0, a1, a2, a3;
        unsigned aaddr = (unsigned)__cvta_generic_to_shared(
            &As_h[(r0 + (aj & 1) * 8 + ari) * HSTR + k0 + (aj >> 1) * 8]);
        asm volatile("ldmatrix.sync.aligned.m8n8.x4.shared.b16 {%0,%1,%2,%3}, [%4];"
                     : "=r"(a0), "=r"(a1), "=r"(a2), "=r"(a3) : "r"(aaddr));
#pragma unroll
        for (int nt = 0; nt < 8; nt++) {
            int boff = (nt * 8 + bri) * HSTR + k0 + bj * 8;
            unsigned b0, b1;
            unsigned baddr = (unsigned)__cvta_generic_to_shared(&Wt0[boff]);
            asm volatile("ldmatrix.sync.aligned.m8n8.x2.shared.b16 {%0,%1}, [%2];"
                         : "=r"(b0), "=r"(b1) : "r"(baddr));
            asm volatile(
                "mma.sync.aligned.m16n8k16.row.col.f32.f16.f16.f32 "
                "{%0,%1,%2,%3}, {%4,%5,%6,%7}, {%8,%9}, {%0,%1,%2,%3};"
                : "+f"(d[nt][0]), "+f"(d[nt][1]), "+f"(d[nt][2]), "+f"(d[nt][3])
                : "r"(a0), "r"(a1), "r"(a2), "r"(a3), "r"(b0), "r"(b1));
            unsigned baddr2 = (unsigned)__cvta_generic_to_shared(&Wt1[boff]);
            asm volatile("ldmatrix.sync.aligned.m8n8.x2.shared.b16 {%0,%1}, [%2];"
                         : "=r"(b0), "=r"(b1) : "r"(baddr2));
            asm volatile(
                "mma.sync.aligned.m16n8k16.row.col.f32.f16.f16.f32 "
                "{%0,%1,%2,%3}, {%4,%5,%6,%7}, {%8,%9}, {%0,%1,%2,%3};"
                : "+f"(d[nt][0]), "+f"(d[nt][1]), "+f"(d[nt][2]), "+f"(d[nt][3])
                : "r"(a0), "r"(a1), "r"(a2), "r"(a3), "r"(b0), "r"(b1));
        }
    }

    // epilogue: d0,d1 -> (row lane>>2, cols n0+2(lane&3)); d2,d3 -> row+8
    int rlo = row0 + r0 + (lane >> 2);
    int rhi = rlo + 8;
    int cq = lane & 3;
#pragma unroll
    for (int nt = 0; nt < 8; nt++) {
        int ci = nt * 4 + cq;  // u32 col index within 32-u32 row
        if (rlo < nrows) {
            __half2 h = __floats2half2_rn(d[nt][0], d[nt][1]);
            hout[(long long)rlo * 32 + ci] = *(unsigned*)&h;
        }
        if (rhi < nrows) {
            __half2 h = __floats2half2_rn(d[nt][2], d[nt][3]);
            hout[(long long)rhi * 32 + ci] = *(unsigned*)&h;
        }
    }
}

// ---------------- mega kernel: [scan | conv0 mma GEMM | scatter] -------------
__global__ void mega_conv0(const uint4* __restrict__ A, const float* __restrict__ W,
                           unsigned* __restrict__ hout,
                           const void* ei, const float* __restrict__ ew,
                           int gemm_blocks) {
    __shared__ __half As_h[128 * HSTR];
    __shared__ __half Wt0[D * HSTR];
    __shared__ __half Wt1[D * HSTR];
    __shared__ int sh[256];
    __shared__ int is_last;
    int tid = threadIdx.x;
    int bid = blockIdx.x;

    if (bid < SCAN_NB) {
        int i0 = bid * SCAN_T + 2 * tid;
        int a = (i0 < NN) ? g_cntn[i0] : 0;
        int b = (i0 + 1 < NN) ? g_cntn[i0 + 1] : 0;
        sh[tid] = a + b;
        __syncthreads();
        for (int off = 1; off < 256; off <<= 1) {
            int t = (tid >= off) ? sh[tid - off] : 0;
            __syncthreads();
            sh[tid] += t;
            __syncthreads();
        }
        int excl = sh[tid] - (a + b);
        if (i0 < NN) g_ptr[i0] = excl;
        if (i0 + 1 < NN) g_ptr[i0 + 1] = excl + a;
        if (tid == 255) {
            g_partials[bid] = sh[255];
            __threadfence();
            int t = atomicAdd(&g_scan_ctr, 1);
            is_last = (t == SCAN_NB - 1);
        }
        __syncthreads();
        if (!is_last) return;
        int v = (tid < SCAN_NB) ? *(volatile int*)&g_partials[tid] : 0;
        sh[tid] = v;
        __syncthreads();
        for (int off = 1; off < 256; off <<= 1) {
            int t = (tid >= off) ? sh[tid - off] : 0;
            __syncthreads();
            sh[tid] += t;
            __syncthreads();
        }
        if (tid < SCAN_NB) g_partials[tid] = sh[tid] - v;
        __threadfence();
        __syncthreads();
        if (tid == 0) atomicExch(&g_scan_done, 1);
        return;
    }

    if (bid < SCAN_NB + gemm_blocks) {
        int gb = bid - SCAN_NB;
        mma_gemm_tile(A, W, hout, gb * 128, NN, As_h, Wt0, Wt1, tid);
        return;
    }

    if (tid == 0) {
        while (atomicAdd(&g_scan_done, 0) == 0) __nanosleep(64);
    }
    __syncthreads();
    {
        int base = (bid - SCAN_NB - gemm_blocks) * 1024 + tid;
        int is64 = g_is64_edge;
        int r[4], c[4]; float w[4];
#pragma unroll
        for (int j = 0; j < 4; j++) {
            int e = base + j * 256;
            if (e < EE) {
                r[j] = load_idx(ei, e, is64);
                c[j] = load_idx(ei, (long long)EE + e, is64);
                w[j] = ew[e];
            } else c[j] = -1;
        }
        float dr[4], dc[4]; int pp[4];
#pragma unroll
        for (int j = 0; j < 4; j++) {
            if (c[j] >= 0) {
                dr[j] = g_deg[r[j]];
                dc[j] = g_deg[c[j]];
                pp[j] = g_ptr[c[j]] + g_partials[c[j] >> 9];
            }
        }
#pragma unroll
        for (int j = 0; j < 4; j++) {
            if (c[j] >= 0) {
                float ir = dr[j] > 0.f ? rsqrtf(dr[j]) : 0.f;
                float ic = dc[j] > 0.f ? rsqrtf(dc[j]) : 0.f;
                int old = atomicSub(&g_cntn[c[j]], 1);
                g_csr[pp[j] + old - 1] = make_int2(r[j], __float_as_int(ir * w[j] * ic));
            }
        }
    }
}

// ---------------- conv GEMM layers 1..3 (mma fp16, fp32 acc) -----------------
__global__ void gemm_conv(const uint4* __restrict__ A, const float* __restrict__ W,
                          unsigned* __restrict__ hout, int nrows) {
    __shared__ __half As_h[128 * HSTR];
    __shared__ __half Wt0[D * HSTR];
    __shared__ __half Wt1[D * HSTR];
    mma_gemm_tile(A, W, hout, blockIdx.x * 128, nrows, As_h, Wt0, Wt1, threadIdx.x);
}

// ---------------- CSR aggregation core: 4x unrolled, 16 edges in flight ------
__device__ __forceinline__ void agg_accum(float acc[8], uint4 u, float nv) {
    __half2* hh = (__half2*)&u;
#pragma unroll
    for (int c = 0; c < 4; c++) {
        float2 f = __half22float2(hh[c]);
        acc[2 * c]     += f.x * nv;
        acc[2 * c + 1] += f.y * nv;
    }
}

__device__ __forceinline__ void agg_core(int node, const uint4* __restrict__ h,
                                         int q, int p, float acc[8]) {
    int s = ptr_of(node), e = ptr_of(node + 1);
    int i = s + q;
    for (; i + 12 < e; i += 16) {
        int2 e0 = g_csr[i];
        int2 e1 = g_csr[i + 4];
        int2 e2 = g_csr[i + 8];
        int2 e3 = g_csr[i + 12];
        uint4 u0 = h[e0.x * 8 + p];
        uint4 u1 = h[e1.x * 8 + p];
        uint4 u2 = h[e2.x * 8 + p];
        uint4 u3 = h[e3.x * 8 + p];
        agg_accum(acc, u0, __int_as_float(e0.y));
        agg_accum(acc, u1, __int_as_float(e1.y));
        agg_accum(acc, u2, __int_as_float(e2.y));
        agg_accum(acc, u3, __int_as_float(e3.y));
    }
    if (i + 4 < e) {
        int2 e0 = g_csr[i];
        int2 e1 = g_csr[i + 4];
        uint4 u0 = h[e0.x * 8 + p];
        uint4 u1 = h[e1.x * 8 + p];
        agg_accum(acc, u0, __int_as_float(e0.y));
        agg_accum(acc, u1, __int_as_float(e1.y));
        i += 8;
    }
    if (i < e) {
        int2 e0 = g_csr[i];
        uint4 u0 = h[e0.x * 8 + p];
        agg_accum(acc, u0, __int_as_float(e0.y));
    }
#pragma unroll
    for (int c = 0; c < 8; c++) {
        acc[c] += __shfl_xor_sync(0xffffffffu, acc[c], 8);
        acc[c] += __shfl_xor_sync(0xffffffffu, acc[c], 16);
    }
}

// agg with fp16 output row (uint4 per lane p)
__global__ void agg_half(const uint4* __restrict__ h,
                         const float* __restrict__ bias, uint4* __restrict__ outp) {
    int node = (blockIdx.x * blockDim.x + threadIdx.x) >> 5;
    if (node >= NN) return;
    int lane = threadIdx.x & 31;
    int q = lane >> 3, p = lane & 7;
    float acc[8] = {};
    agg_core(node, h, q, p, acc);
    if (q == 0) {
        float4 b0 = *(const float4*)&bias[8 * p];
        float4 b1 = *(const float4*)&bias[8 * p + 4];
        float o[8];
        o[0] = fmaxf(acc[0] + b0.x, 0.f); o[1] = fmaxf(acc[1] + b0.y, 0.f);
        o[2] = fmaxf(acc[2] + b0.z, 0.f); o[3] = fmaxf(acc[3] + b0.w, 0.f);
        o[4] = fmaxf(acc[4] + b1.x, 0.f); o[5] = fmaxf(acc[5] + b1.y, 0.f);
        o[6] = fmaxf(acc[6] + b1.z, 0.f); o[7] = fmaxf(acc[7] + b1.w, 0.f);
        __half2 h0 = __floats2half2_rn(o[0], o[1]);
        __half2 h1 = __floats2half2_rn(o[2], o[3]);
        __half2 h2 = __floats2half2_rn(o[4], o[5]);
        __half2 h3 = __floats2half2_rn(o[6], o[7]);
        uint4 u;
        u.x = *(unsigned*)&h0;
        u.y = *(unsigned*)&h1;
        u.z = *(unsigned*)&h2;
        u.w = *(unsigned*)&h3;
        outp[node * 8 + p] = u;
    }
}

__device__ __forceinline__ void red_add_v4(float4* addr, float4 v) {
    asm volatile("red.global.add.v4.f32 [%0], {%1,%2,%3,%4};"
                 :: "l"(addr), "f"(v.x), "f"(v.y), "f"(v.z), "f"(v.w)
                 : "memory");
}

// Last layer: aggregate + bias + relu + mean-pool accumulate (fp32 path).
__global__ void agg_pool(const uint4* __restrict__ h,
                         const float* __restrict__ bias, const void* batch) {
    int node = (blockIdx.x * blockDim.x + threadIdx.x) >> 5;
    if (node >= NN) return;
    int lane = threadIdx.x & 31;
    int q = lane >> 3, p = lane & 7;
    float acc[8] = {};
    agg_core(node, h, q, p, acc);
    if (q == 0) {
        int g = load_idx(batch, node, g_is64_batch);
        float4 b0 = *(const float4*)&bias[8 * p];
        float4 b1 = *(const float4*)&bias[8 * p + 4];
        float4 o0 = make_float4(fmaxf(acc[0] + b0.x, 0.f), fmaxf(acc[1] + b0.y, 0.f),
                                fmaxf(acc[2] + b0.z, 0.f), fmaxf(acc[3] + b0.w, 0.f));
        float4 o1 = make_float4(fmaxf(acc[4] + b1.x, 0.f), fmaxf(acc[5] + b1.y, 0.f),
                                fmaxf(acc[6] + b1.z, 0.f), fmaxf(acc[7] + b1.w, 0.f));
        float* row = g_sums + g * D + 8 * p;
        red_add_v4((float4*)row, o0);
        red_add_v4((float4*)(row + 4), o1);
        if (p == 0) atomicAdd(&g_cnt[g], 1.0f);
    }
}

// ---------------- fused MLP tail: lin1 -> fc0 -> fc1 -> lin2 ----------------
__global__ void tail_kernel(const float* __restrict__ W1, const float* __restrict__ b1,
                            const float* __restrict__ fcw, const float* __restrict__ fcb,
                            const float* __restrict__ w2, const float* __restrict__ b2,
                            float* __restrict__ out) {
    int g = blockIdx.x, tid = threadIdx.x;  // 64 threads
    __shared__ float buf[2][64];
    __shared__ float red[64];

    buf[0][tid] = g_sums[g * D + tid] / fmaxf(g_cnt[g], 1.f);
    __syncthreads();
    {
        float acc = 0.f;
#pragma unroll
        for (int k = 0; k < 64; k++) acc += buf[0][k] * W1[k * D + tid];
        buf[1][tid] = fmaxf(acc + b1[tid], 0.f);
        __syncthreads();
    }
    int cur = 1;
    for (int L = 0; L < 2; L++) {
        const float* W = fcw + L * D * D;
        float acc = 0.f;
#pragma unroll
        for (int k = 0; k < 64; k++) acc += buf[cur][k] * W[k * D + tid];
        __syncthreads();
        buf[cur ^ 1][tid] = fmaxf(acc + fcb[L * D + tid], 0.f);
        cur ^= 1;
        __syncthreads();
    }
    red[tid] = buf[cur][tid] * w2[tid];
    __syncthreads();
    if (tid < 32) {
        float s = red[tid] + red[tid + 32];
#pragma unroll
        for (int off = 16; off; off >>= 1) s += __shfl_down_sync(0xffffffffu, s, off);
        if (tid == 0) out[g] = s + b2[0];
    }
}

// ---------------- launch ----------------
extern "C" void kernel_launch(void* const* d_in, const int* in_sizes, int n_in,
                              void* d_out, int out_size) {
    const float* x      = (const float*)d_in[0];
    const void*  ei     = d_in[1];
    const float* ew     = (const float*)d_in[2];
    const void*  batch  = d_in[3];
    const float* lin0_w = (const float*)d_in[4];
    const float* lin0_b = (const float*)d_in[5];
    const float* conv_w = (const float*)d_in[6];
    const float* conv_b = (const float*)d_in[7];
    const float* lin1_w = (const float*)d_in[8];
    const float* lin1_b = (const float*)d_in[9];
    const float* fc_w   = (const float*)d_in[10];
    const float* fc_b   = (const float*)d_in[11];
    const float* lin2_w = (const float*)d_in[12];
    const float* lin2_b = (const float*)d_in[13];
    float* out = (float*)d_out;

    uint4 *p_out0, *p_h, *p_aggA, *p_aggB;
    cudaGetSymbolAddress((void**)&p_out0, g_out0);
    cudaGetSymbolAddress((void**)&p_h,    g_hh);
    cudaGetSymbolAddress((void**)&p_aggA, g_aggA);
    cudaGetSymbolAddress((void**)&p_aggB, g_aggB);

    // init: zero deg/cntn/sums/cnt/scan flags + dtype detect
    init_kernel<<<(NN + 255) / 256, 256>>>((const int*)ei, (const int*)batch);

    // fused lin0 GEMM (fp16 out) + degree histogram (overlapped, 4 edges/thread)
    const int GB = (NN + 127) / 128;            // 782 gemm blocks
    const int DB4 = (EE + 1023) / 1024;         // 1563 edge blocks
    fused_lin0_deg<<<GB + DB4, 256>>>(x, lin0_w, lin0_b, (unsigned*)p_out0, ei, ew, GB);

    // mega: scan (196) | conv-0 mma GEMM (782) | scatter (1563) — one launch
    mega_conv0<<<SCAN_NB + GB + DB4, 256>>>(p_out0, conv_w, (unsigned*)p_h, ei, ew, GB);

    uint4* bufs[2] = {p_aggA, p_aggB};
    const int AGB = (NN * 32) / 256;  // 12500 blocks
    const uint4* Ain = nullptr;
    for (int i = 0; i < 4; i++) {
        if (i > 0) {
            gemm_conv<<<GB, 256>>>(Ain, conv_w + i * D * D, (unsigned*)p_h, NN);
        }
        if (i < 3) {
            uint4* agg = bufs[i & 1];
            agg_half<<<AGB, 256>>>(p_h, conv_b + i * D, agg);
            Ain = agg;
        } else {
            agg_pool<<<AGB, 256>>>(p_h, conv_b + i * D, batch);
        }
    }

    tail_kernel<<<GG, 64>>>(lin1_w, lin1_b, fc_w, fc_b, lin2_w, lin2_b, out);
}

// round 17
// speedup vs baseline: 1.8733x; 1.0446x over previous
#include <cuda_runtime.h>
#include <cuda_fp16.h>

#define NN 100000
#define EE 1600000
#define FIN 100
#define D 64
#define GG 500
#define SCAN_T 512
#define SCAN_NB ((NN + SCAN_T - 1) / SCAN_T)
#define HSTR 72    // half stride for conv mma tiles (144B rows, conflict-free)
#define LSTR 120   // half stride for lin0 mma tiles (240B rows, conflict-free)
#define KPAD 112   // lin0 K padded to 7x16
#define L0_SMEM ((128 * LSTR + 2 * D * LSTR) * 2)  // 61440 B

// ---------------- scratch (device globals; no allocs allowed) ----------------
__device__ float g_deg[NN];
__device__ int   g_cntn[NN];
__device__ int   g_ptr[NN + 1];
__device__ int   g_partials[SCAN_NB];
__device__ int2  g_csr[EE];        // packed {row, norm_bits}
__device__ uint4 g_out0[NN * 8];   // lin0 out, fp16 (64 halves = 8 uint4/row)
__device__ uint4 g_hh[NN * 8];     // h fp16
__device__ uint4 g_aggA[NN * 8];   // agg out ping, fp16
__device__ uint4 g_aggB[NN * 8];   // agg out pong, fp16
__device__ float g_sums[GG * D];
__device__ float g_cnt[GG];
__device__ int g_is64_edge;
__device__ int g_is64_batch;
__device__ int g_scan_ctr;
__device__ int g_scan_done;

__device__ __forceinline__ int load_idx(const void* p, long long i, int is64) {
    return is64 ? (int)((const long long*)p)[i] : ((const int*)p)[i];
}

// ptr fixup inlined: final ptr(n) = g_ptr[n] + partials[n>>9]
__device__ __forceinline__ int ptr_of(int n) {
    return (n == NN) ? EE : g_ptr[n] + g_partials[n >> 9];
}

// ---------------- init: zero scratch + dtype detect (one kernel) -------------
__global__ void init_kernel(const int* ei, const int* bat) {
    int t = blockIdx.x * 256 + threadIdx.x;
    if (t < NN) { g_deg[t] = 0.f; g_cntn[t] = 0; }
    if (t < GG * D) g_sums[t] = 0.f;
    if (t < GG) g_cnt[t] = 0.f;
    if (t == 0) { g_scan_ctr = 0; g_scan_done = 0; }
    if (blockIdx.x == 0 && threadIdx.x < 32) {
        int i = threadIdx.x;
        int nz_e = 0, nz_b = 0;
        for (int j = i; j < 128; j += 32) {
            int w = 1 + 700 * j;  // always odd, < NN words
            nz_e |= (ei[w] != 0);
            nz_b |= (bat[w] != 0);
        }
        unsigned be = __ballot_sync(0xffffffffu, nz_e);
        unsigned bb = __ballot_sync(0xffffffffu, nz_b);
        if (i == 0) {
            g_is64_edge = (be == 0);
            g_is64_batch = (bb == 0);
        }
    }
}

// ---------------- fused: lin0 mma GEMM (fp16 frags, fp32 acc) + degree hist --
// x staged fp32->fp16 (one rounding); W exact-split Whi+Wlo (no extra error).
// K=100 padded to 112 (7 k-chunks). Dynamic smem: As 128x120 | Wt0,Wt1 64x120.
__global__ void fused_lin0_deg(const float* __restrict__ A, const float* __restrict__ W,
                               const float* __restrict__ biasC, unsigned* __restrict__ C,
                               const void* ei, const float* __restrict__ ew,
                               int gemm_blocks) {
    extern __shared__ __half sm[];
    int tid = threadIdx.x;

    if (blockIdx.x >= gemm_blocks) {
        int base = (blockIdx.x - gemm_blocks) * 1024 + tid;
        int is64 = g_is64_edge;
        int c[4]; float w[4];
#pragma unroll
        for (int j = 0; j < 4; j++) {
            int e = base + j * 256;
            if (e < EE) {
                c[j] = load_idx(ei, (long long)EE + e, is64);
                w[j] = ew[e];
            } else c[j] = -1;
        }
#pragma unroll
        for (int j = 0; j < 4; j++) {
            if (c[j] >= 0) {
                atomicAdd(&g_deg[c[j]], w[j]);
                atomicAdd(&g_cntn[c[j]], 1);
            }
        }
        return;
    }

    __half* As_h = sm;                      // 128 x LSTR
    __half* Wt0 = sm + 128 * LSTR;          // 64 x LSTR (transposed [n][k])
    __half* Wt1 = Wt0 + D * LSTR;

    int row0 = blockIdx.x * 128;
    // stage W exact split, transposed, zero-padded K
    for (int i = tid; i < KPAD * D; i += 256) {
        int k = i >> 6, n = i & 63;
        float w = (k < FIN) ? W[k * D + n] : 0.f;
        __half hi = __float2half_rn(w);
        Wt0[n * LSTR + k] = hi;
        Wt1[n * LSTR + k] = __float2half_rn(w - __half2float(hi));
    }
    // stage x -> fp16 (128 rows x 100, pad to 112)
    for (int i = tid; i < 128 * 50; i += 256) {
        int r = i / 50, k2 = i - r * 50;
        int gr = row0 + r;
        float2 v = make_float2(0.f, 0.f);
        if (gr < NN) v = *(const float2*)&A[(long long)gr * FIN + 2 * k2];
        As_h[r * LSTR + 2 * k2] = __float2half_rn(v.x);
        As_h[r * LSTR + 2 * k2 + 1] = __float2half_rn(v.y);
    }
    for (int i = tid; i < 128 * 12; i += 256) {
        int r = i / 12, k = FIN + i - (i / 12) * 12;
        As_h[r * LSTR + k] = __float2half_rn(0.f);
    }
    __syncthreads();

    int wid = tid >> 5, lane = tid & 31;
    int r0w = wid * 16;
    float d[8][4] = {};
    int aj = lane >> 3, ari = lane & 7;
    int l15 = lane & 15;
    int bj = l15 >> 3, bri = l15 & 7;

#pragma unroll
    for (int kc = 0; kc < 7; kc++) {
        int k0 = kc * 16;
        unsigned a0, a1, a2, a3;
        unsigned aaddr = (unsigned)__cvta_generic_to_shared(
            &As_h[(r0w + (aj & 1) * 8 + ari) * LSTR + k0 + (aj >> 1) * 8]);
        asm volatile("ldmatrix.sync.aligned.m8n8.x4.shared.b16 {%0,%1,%2,%3}, [%4];"
                     : "=r"(a0), "=r"(a1), "=r"(a2), "=r"(a3) : "r"(aaddr));
#pragma unroll
        for (int nt = 0; nt < 8; nt++) {
            int boff = (nt * 8 + bri) * LSTR + k0 + bj * 8;
            unsigned b0, b1;
            unsigned baddr = (unsigned)__cvta_generic_to_shared(&Wt0[boff]);
            asm volatile("ldmatrix.sync.aligned.m8n8.x2.shared.b16 {%0,%1}, [%2];"
                         : "=r"(b0), "=r"(b1) : "r"(baddr));
            asm volatile(
                "mma.sync.aligned.m16n8k16.row.col.f32.f16.f16.f32 "
                "{%0,%1,%2,%3}, {%4,%5,%6,%7}, {%8,%9}, {%0,%1,%2,%3};"
                : "+f"(d[nt][0]), "+f"(d[nt][1]), "+f"(d[nt][2]), "+f"(d[nt][3])
                : "r"(a0), "r"(a1), "r"(a2), "r"(a3), "r"(b0), "r"(b1));
            unsigned baddr2 = (unsigned)__cvta_generic_to_shared(&Wt1[boff]);
            asm volatile("ldmatrix.sync.aligned.m8n8.x2.shared.b16 {%0,%1}, [%2];"
                         : "=r"(b0), "=r"(b1) : "r"(baddr2));
            asm volatile(
                "mma.sync.aligned.m16n8k16.row.col.f32.f16.f16.f32 "
                "{%0,%1,%2,%3}, {%4,%5,%6,%7}, {%8,%9}, {%0,%1,%2,%3};"
                : "+f"(d[nt][0]), "+f"(d[nt][1]), "+f"(d[nt][2]), "+f"(d[nt][3])
                : "r"(a0), "r"(a1), "r"(a2), "r"(a3), "r"(b0), "r"(b1));
        }
    }

    // epilogue: bias + relu + fp16 store
    int rlo = row0 + r0w + (lane >> 2);
    int rhi = rlo + 8;
    int cq = lane & 3;
#pragma unroll
    for (int nt = 0; nt < 8; nt++) {
        int c0 = nt * 8 + 2 * cq;
        float bx = biasC[c0], by = biasC[c0 + 1];
        int ci = nt * 4 + cq;
        if (rlo < NN) {
            __half2 h = __floats2half2_rn(fmaxf(d[nt][0] + bx, 0.f),
                                          fmaxf(d[nt][1] + by, 0.f));
            C[(long long)rlo * 32 + ci] = *(unsigned*)&h;
        }
        if (rhi < NN) {
            __half2 h = __floats2half2_rn(fmaxf(d[nt][2] + bx, 0.f),
                                          fmaxf(d[nt][3] + by, 0.f));
            C[(long long)rhi * 32 + ci] = *(unsigned*)&h;
        }
    }
}

// ---------------- mma conv GEMM tile: h_out[128,64] = A[128,64]h @ W[64,64] --
__device__ __forceinline__ void mma_gemm_tile(
    const uint4* __restrict__ A, const float* __restrict__ W,
    unsigned* __restrict__ hout, int row0, int nrows,
    __half* As_h, __half* Wt0, __half* Wt1, int tid) {
    for (int i = tid; i < D * D; i += 256) {
        int k = i >> 6, n = i & 63;
        float w = W[i];
        __half hi = __float2half_rn(w);
        float res = w - __half2float(hi);
        Wt0[n * HSTR + k] = hi;
        Wt1[n * HSTR + k] = __float2half_rn(res);
    }
    for (int i = tid; i < 128 * 8; i += 256) {
        int r = i >> 3, c8 = i & 7;
        int gr = row0 + r;
        uint4 v = make_uint4(0u, 0u, 0u, 0u);
        if (gr < nrows) v = A[(long long)gr * 8 + c8];
        *(uint4*)&As_h[r * HSTR + c8 * 8] = v;
    }
    __syncthreads();

    int wid = tid >> 5, lane = tid & 31;
    int r0 = wid * 16;
    float d[8][4] = {};
    int aj = lane >> 3, ari = lane & 7;
    int l15 = lane & 15;
    int bj = l15 >> 3, bri = l15 & 7;

#pragma unroll
    for (int kc = 0; kc < 4; kc++) {
        int k0 = kc * 16;
        unsigned a0, a1, a2, a3;
        unsigned aaddr = (unsigned)__cvta_generic_to_shared(
            &As_h[(r0 + (aj & 1) * 8 + ari) * HSTR + k0 + (aj >> 1) * 8]);
        asm volatile("ldmatrix.sync.aligned.m8n8.x4.shared.b16 {%0,%1,%2,%3}, [%4];"
                     : "=r"(a0), "=r"(a1), "=r"(a2), "=r"(a3) : "r"(aaddr));
#pragma unroll
        for (int nt = 0; nt < 8; nt++) {
            int boff = (nt * 8 + bri) * HSTR + k0 + bj * 8;
            unsigned b0, b1;
            unsigned baddr = (unsigned)__cvta_generic_to_shared(&Wt0[boff]);
            asm volatile("ldmatrix.sync.aligned.m8n8.x2.shared.b16 {%0,%1}, [%2];"
                         : "=r"(b0), "=r"(b1) : "r"(baddr));
            asm volatile(
                "mma.sync.aligned.m16n8k16.row.col.f32.f16.f16.f32 "
                "{%0,%1,%2,%3}, {%4,%5,%6,%7}, {%8,%9}, {%0,%1,%2,%3};"
                : "+f"(d[nt][0]), "+f"(d[nt][1]), "+f"(d[nt][2]), "+f"(d[nt][3])
                : "r"(a0), "r"(a1), "r"(a2), "r"(a3), "r"(b0), "r"(b1));
            unsigned baddr2 = (unsigned)__cvta_generic_to_shared(&Wt1[boff]);
            asm volatile("ldmatrix.sync.aligned.m8n8.x2.shared.b16 {%0,%1}, [%2];"
                         : "=r"(b0), "=r"(b1) : "r"(baddr2));
            asm volatile(
                "mma.sync.aligned.m16n8k16.row.col.f32.f16.f16.f32 "
                "{%0,%1,%2,%3}, {%4,%5,%6,%7}, {%8,%9}, {%0,%1,%2,%3};"
                : "+f"(d[nt][0]), "+f"(d[nt][1]), "+f"(d[nt][2]), "+f"(d[nt][3])
                : "r"(a0), "r"(a1), "r"(a2), "r"(a3), "r"(b0), "r"(b1));
        }
    }

    int rlo = row0 + r0 + (lane >> 2);
    int rhi = rlo + 8;
    int cq = lane & 3;
#pragma unroll
    for (int nt = 0; nt < 8; nt++) {
        int ci = nt * 4 + cq;
        if (rlo < nrows) {
            __half2 h = __floats2half2_rn(d[nt][0], d[nt][1]);
            hout[(long long)rlo * 32 + ci] = *(unsigned*)&h;
        }
        if (rhi < nrows) {
            __half2 h = __floats2half2_rn(d[nt][2], d[nt][3]);
            hout[(long long)rhi * 32 + ci] = *(unsigned*)&h;
        }
    }
}

// ---------------- mega kernel: [scan | conv0 mma GEMM | scatter] -------------
__global__ void mega_conv0(const uint4* __restrict__ A, const float* __restrict__ W,
                           unsigned* __restrict__ hout,
                           const void* ei, const float* __restrict__ ew,
                           int gemm_blocks) {
    __shared__ __half As_h[128 * HSTR];
    __shared__ __half Wt0[D * HSTR];
    __shared__ __half Wt1[D * HSTR];
    __shared__ int sh[256];
    __shared__ int is_last;
    int tid = threadIdx.x;
    int bid = blockIdx.x;

    if (bid < SCAN_NB) {
        int i0 = bid * SCAN_T + 2 * tid;
        int a = (i0 < NN) ? g_cntn[i0] : 0;
        int b = (i0 + 1 < NN) ? g_cntn[i0 + 1] : 0;
        sh[tid] = a + b;
        __syncthreads();
        for (int off = 1; off < 256; off <<= 1) {
            int t = (tid >= off) ? sh[tid - off] : 0;
            __syncthreads();
            sh[tid] += t;
            __syncthreads();
        }
        int excl = sh[tid] - (a + b);
        if (i0 < NN) g_ptr[i0] = excl;
        if (i0 + 1 < NN) g_ptr[i0 + 1] = excl + a;
        if (tid == 255) {
            g_partials[bid] = sh[255];
            __threadfence();
            int t = atomicAdd(&g_scan_ctr, 1);
            is_last = (t == SCAN_NB - 1);
        }
        __syncthreads();
        if (!is_last) return;
        int v = (tid < SCAN_NB) ? *(volatile int*)&g_partials[tid] : 0;
        sh[tid] = v;
        __syncthreads();
        for (int off = 1; off < 256; off <<= 1) {
            int t = (tid >= off) ? sh[tid - off] : 0;
            __syncthreads();
            sh[tid] += t;
            __syncthreads();
        }
        if (tid < SCAN_NB) g_partials[tid] = sh[tid] - v;
        __threadfence();
        __syncthreads();
        if (tid == 0) atomicExch(&g_scan_done, 1);
        return;
    }

    if (bid < SCAN_NB + gemm_blocks) {
        int gb = bid - SCAN_NB;
        mma_gemm_tile(A, W, hout, gb * 128, NN, As_h, Wt0, Wt1, tid);
        return;
    }

    if (tid == 0) {
        while (atomicAdd(&g_scan_done, 0) == 0) __nanosleep(64);
    }
    __syncthreads();
    {
        int base = (bid - SCAN_NB - gemm_blocks) * 1024 + tid;
        int is64 = g_is64_edge;
        int r[4], c[4]; float w[4];
#pragma unroll
        for (int j = 0; j < 4; j++) {
            int e = base + j * 256;
            if (e < EE) {
                r[j] = load_idx(ei, e, is64);
                c[j] = load_idx(ei, (long long)EE + e, is64);
                w[j] = ew[e];
            } else c[j] = -1;
        }
        float dr[4], dc[4]; int pp[4];
#pragma unroll
        for (int j = 0; j < 4; j++) {
            if (c[j] >= 0) {
                dr[j] = g_deg[r[j]];
                dc[j] = g_deg[c[j]];
                pp[j] = g_ptr[c[j]] + g_partials[c[j] >> 9];
            }
        }
#pragma unroll
        for (int j = 0; j < 4; j++) {
            if (c[j] >= 0) {
                float ir = dr[j] > 0.f ? rsqrtf(dr[j]) : 0.f;
                float ic = dc[j] > 0.f ? rsqrtf(dc[j]) : 0.f;
                int old = atomicSub(&g_cntn[c[j]], 1);
                g_csr[pp[j] + old - 1] = make_int2(r[j], __float_as_int(ir * w[j] * ic));
            }
        }
    }
}

// ---------------- conv GEMM layers 1..3 (mma fp16, fp32 acc) -----------------
__global__ void gemm_conv(const uint4* __restrict__ A, const float* __restrict__ W,
                          unsigned* __restrict__ hout, int nrows) {
    __shared__ __half As_h[128 * HSTR];
    __shared__ __half Wt0[D * HSTR];
    __shared__ __half Wt1[D * HSTR];
    mma_gemm_tile(A, W, hout, blockIdx.x * 128, nrows, As_h, Wt0, Wt1, threadIdx.x);
}

// ---------------- CSR aggregation core: 4x unrolled, 16 edges in flight ------
__device__ __forceinline__ void agg_accum(float acc[8], uint4 u, float nv) {
    __half2* hh = (__half2*)&u;
#pragma unroll
    for (int c = 0; c < 4; c++) {
        float2 f = __half22float2(hh[c]);
        acc[2 * c]     += f.x * nv;
        acc[2 * c + 1] += f.y * nv;
    }
}

__device__ __forceinline__ void agg_core(int node, const uint4* __restrict__ h,
                                         int q, int p, float acc[8]) {
    int s = ptr_of(node), e = ptr_of(node + 1);
    int i = s + q;
    for (; i + 12 < e; i += 16) {
        int2 e0 = g_csr[i];
        int2 e1 = g_csr[i + 4];
        int2 e2 = g_csr[i + 8];
        int2 e3 = g_csr[i + 12];
        uint4 u0 = h[e0.x * 8 + p];
        uint4 u1 = h[e1.x * 8 + p];
        uint4 u2 = h[e2.x * 8 + p];
        uint4 u3 = h[e3.x * 8 + p];
        agg_accum(acc, u0, __int_as_float(e0.y));
        agg_accum(acc, u1, __int_as_float(e1.y));
        agg_accum(acc, u2, __int_as_float(e2.y));
        agg_accum(acc, u3, __int_as_float(e3.y));
    }
    if (i + 4 < e) {
        int2 e0 = g_csr[i];
        int2 e1 = g_csr[i + 4];
        uint4 u0 = h[e0.x * 8 + p];
        uint4 u1 = h[e1.x * 8 + p];
        agg_accum(acc, u0, __int_as_float(e0.y));
        agg_accum(acc, u1, __int_as_float(e1.y));
        i += 8;
    }
    if (i < e) {
        int2 e0 = g_csr[i];
        uint4 u0 = h[e0.x * 8 + p];
        agg_accum(acc, u0, __int_as_float(e0.y));
    }
#pragma unroll
    for (int c = 0; c < 8; c++) {
        acc[c] += __shfl_xor_sync(0xffffffffu, acc[c], 8);
        acc[c] += __shfl_xor_sync(0xffffffffu, acc[c], 16);
    }
}

// agg with fp16 output row (uint4 per lane p)
__global__ void agg_half(const uint4* __restrict__ h,
                         const float* __restrict__ bias, uint4* __restrict__ outp) {
    int node = (blockIdx.x * blockDim.x + threadIdx.x) >> 5;
    if (node >= NN) return;
    int lane = threadIdx.x & 31;
    int q = lane >> 3, p = lane & 7;
    float acc[8] = {};
    agg_core(node, h, q, p, acc);
    if (q == 0) {
        float4 b0 = *(const float4*)&bias[8 * p];
        float4 b1 = *(const float4*)&bias[8 * p + 4];
        float o[8];
        o[0] = fmaxf(acc[0] + b0.x, 0.f); o[1] = fmaxf(acc[1] + b0.y, 0.f);
        o[2] = fmaxf(acc[2] + b0.z, 0.f); o[3] = fmaxf(acc[3] + b0.w, 0.f);
        o[4] = fmaxf(acc[4] + b1.x, 0.f); o[5] = fmaxf(acc[5] + b1.y, 0.f);
        o[6] = fmaxf(acc[6] + b1.z, 0.f); o[7] = fmaxf(acc[7] + b1.w, 0.f);
        __half2 h0 = __floats2half2_rn(o[0], o[1]);
        __half2 h1 = __floats2half2_rn(o[2], o[3]);
        __half2 h2 = __floats2half2_rn(o[4], o[5]);
        __half2 h3 = __floats2half2_rn(o[6], o[7]);
        uint4 u;
        u.x = *(unsigned*)&h0;
        u.y = *(unsigned*)&h1;
        u.z = *(unsigned*)&h2;
        u.w = *(unsigned*)&h3;
        outp[node * 8 + p] = u;
    }
}

__device__ __forceinline__ void red_add_v4(float4* addr, float4 v) {
    asm volatile("red.global.add.v4.f32 [%0], {%1,%2,%3,%4};"
                 :: "l"(addr), "f"(v.x), "f"(v.y), "f"(v.z), "f"(v.w)
                 : "memory");
}

// Last layer: aggregate + bias + relu + mean-pool accumulate (fp32 path).
__global__ void agg_pool(const uint4* __restrict__ h,
                         const float* __restrict__ bias, const void* batch) {
    int node = (blockIdx.x * blockDim.x + threadIdx.x) >> 5;
    if (node >= NN) return;
    int lane = threadIdx.x & 31;
    int q = lane >> 3, p = lane & 7;
    float acc[8] = {};
    agg_core(node, h, q, p, acc);
    if (q == 0) {
        int g = load_idx(batch, node, g_is64_batch);
        float4 b0 = *(const float4*)&bias[8 * p];
        float4 b1 = *(const float4*)&bias[8 * p + 4];
        float4 o0 = make_float4(fmaxf(acc[0] + b0.x, 0.f), fmaxf(acc[1] + b0.y, 0.f),
                                fmaxf(acc[2] + b0.z, 0.f), fmaxf(acc[3] + b0.w, 0.f));
        float4 o1 = make_float4(fmaxf(acc[4] + b1.x, 0.f), fmaxf(acc[5] + b1.y, 0.f),
                                fmaxf(acc[6] + b1.z, 0.f), fmaxf(acc[7] + b1.w, 0.f));
        float* row = g_sums + g * D + 8 * p;
        red_add_v4((float4*)row, o0);
        red_add_v4((float4*)(row + 4), o1);
        if (p == 0) atomicAdd(&g_cnt[g], 1.0f);
    }
}

// ---------------- fused MLP tail: lin1 -> fc0 -> fc1 -> lin2 ----------------
__global__ void tail_kernel(const float* __restrict__ W1, const float* __restrict__ b1,
                            const float* __restrict__ fcw, const float* __restrict__ fcb,
                            const float* __restrict__ w2, const float* __restrict__ b2,
                            float* __restrict__ out) {
    int g = blockIdx.x, tid = threadIdx.x;  // 64 threads
    __shared__ float buf[2][64];
    __shared__ float red[64];

    buf[0][tid] = g_sums[g * D + tid] / fmaxf(g_cnt[g], 1.f);
    __syncthreads();
    {
        float acc = 0.f;
#pragma unroll
        for (int k = 0; k < 64; k++) acc += buf[0][k] * W1[k * D + tid];
        buf[1][tid] = fmaxf(acc + b1[tid], 0.f);
        __syncthreads();
    }
    int cur = 1;
    for (int L = 0; L < 2; L++) {
        const float* W = fcw + L * D * D;
        float acc = 0.f;
#pragma unroll
        for (int k = 0; k < 64; k++) acc += buf[cur][k] * W[k * D + tid];
        __syncthreads();
        buf[cur ^ 1][tid] = fmaxf(acc + fcb[L * D + tid], 0.f);
        cur ^= 1;
        __syncthreads();
    }
    red[tid] = buf[cur][tid] * w2[tid];
    __syncthreads();
    if (tid < 32) {
        float s = red[tid] + red[tid + 32];
#pragma unroll
        for (int off = 16; off; off >>= 1) s += __shfl_down_sync(0xffffffffu, s, off);
        if (tid == 0) out[g] = s + b2[0];
    }
}

// ---------------- launch ----------------
extern "C" void kernel_launch(void* const* d_in, const int* in_sizes, int n_in,
                              void* d_out, int out_size) {
    const float* x      = (const float*)d_in[0];
    const void*  ei     = d_in[1];
    const float* ew     = (const float*)d_in[2];
    const void*  batch  = d_in[3];
    const float* lin0_w = (const float*)d_in[4];
    const float* lin0_b = (const float*)d_in[5];
    const float* conv_w = (const float*)d_in[6];
    const float* conv_b = (const float*)d_in[7];
    const float* lin1_w = (const float*)d_in[8];
    const float* lin1_b = (const float*)d_in[9];
    const float* fc_w   = (const float*)d_in[10];
    const float* fc_b   = (const float*)d_in[11];
    const float* lin2_w = (const float*)d_in[12];
    const float* lin2_b = (const float*)d_in[13];
    float* out = (float*)d_out;

    uint4 *p_out0, *p_h, *p_aggA, *p_aggB;
    cudaGetSymbolAddress((void**)&p_out0, g_out0);
    cudaGetSymbolAddress((void**)&p_h,    g_hh);
    cudaGetSymbolAddress((void**)&p_aggA, g_aggA);
    cudaGetSymbolAddress((void**)&p_aggB, g_aggB);

    cudaFuncSetAttribute(fused_lin0_deg,
                         cudaFuncAttributeMaxDynamicSharedMemorySize, L0_SMEM);

    // init: zero deg/cntn/sums/cnt/scan flags + dtype detect
    init_kernel<<<(NN + 255) / 256, 256>>>((const int*)ei, (const int*)batch);

    // fused lin0 mma GEMM (fp16 out) + degree histogram (overlapped)
    const int GB = (NN + 127) / 128;            // 782 gemm blocks
    const int DB4 = (EE + 1023) / 1024;         // 1563 edge blocks
    fused_lin0_deg<<<GB + DB4, 256, L0_SMEM>>>(x, lin0_w, lin0_b, (unsigned*)p_out0,
                                               ei, ew, GB);

    // mega: scan (196) | conv-0 mma GEMM (782) | scatter (1563) — one launch
    mega_conv0<<<SCAN_NB + GB + DB4, 256>>>(p_out0, conv_w, (unsigned*)p_h, ei, ew, GB);

    uint4* bufs[2] = {p_aggA, p_aggB};
    const int AGB = (NN * 32) / 256;  // 12500 blocks
    const uint4* Ain = nullptr;
    for (int i = 0; i < 4; i++) {
        if (i > 0) {
            gemm_conv<<<GB, 256>>>(Ain, conv_w + i * D * D, (unsigned*)p_h, NN);
        }
        if (i < 3) {
            uint4* agg = bufs[i & 1];
            agg_half<<<AGB, 256>>>(p_h, conv_b + i * D, agg);
            Ain = agg;
        } else {
            agg_pool<<<AGB, 256>>>(p_h, conv_b + i * D, batch);
        }
    }

    tail_kernel<<<GG, 64>>>(lin1_w, lin1_b, fc_w, fc_b, lin2_w, lin2_b, out);
}